// round 11
// baseline (speedup 1.0000x reference)
#include <cuda_runtime.h>
#include <cuda_fp16.h>
#include <cstdint>
#include <math.h>

#define T_ 5
#define H_ 64
#define W_ 96
#define HW_ (H_ * W_)
#define HEADS_ 8
#define LVLS_ 5
#define PTS_ 4
#define NPIX_ (T_ * HW_)
#define PW_ (W_ + 2)            // 98
#define PH_ (H_ + 2)            // 66
#define PPIX_ (PW_ * PH_)       // 6468

// ================= helpers =================
__device__ __forceinline__ uint32_t smem_u32(const void* p) {
    uint32_t a;
    asm("{ .reg .u64 t; cvta.to.shared.u64 t, %1; cvt.u32.u64 %0, t; }" : "=r"(a) : "l"(p));
    return a;
}
__device__ __forceinline__ void ldsm4(uint32_t* r, uint32_t addr) {
    asm volatile("ldmatrix.sync.aligned.m8n8.x4.shared.b16 {%0,%1,%2,%3}, [%4];"
        : "=r"(r[0]), "=r"(r[1]), "=r"(r[2]), "=r"(r[3]) : "r"(addr));
}
__device__ __forceinline__ void mma16816(float* c, const uint32_t* a, uint32_t b0, uint32_t b1) {
    asm volatile(
        "mma.sync.aligned.m16n8k16.row.col.f32.f16.f16.f32 "
        "{%0,%1,%2,%3}, {%4,%5,%6,%7}, {%8,%9}, {%0,%1,%2,%3};"
        : "+f"(c[0]), "+f"(c[1]), "+f"(c[2]), "+f"(c[3])
        : "r"(a[0]), "r"(a[1]), "r"(a[2]), "r"(a[3]), "r"(b0), "r"(b1));
}
// cp.async 16B with zero-fill when !ok
__device__ __forceinline__ void cp16(uint32_t dst, const void* src, int ok) {
    asm volatile(
        "{\n\t.reg .pred p;\n\tsetp.ne.s32 p, %2, 0;\n\t"
        "@p cp.async.cg.shared.global [%0], [%1], 16;\n\t"
        "@!p cp.async.cg.shared.global [%0], [%1], 16, 0;\n\t}"
        :: "r"(dst), "l"(src), "r"(ok) : "memory");
}
__device__ __forceinline__ void cp_async_wait_all() {
    asm volatile("cp.async.commit_group;\ncp.async.wait_group 0;" ::: "memory");
}

// ================= scratch =================
__device__ __align__(16) __half g_xfh[(size_t)T_ * PPIX_ * 256], g_xfl[(size_t)T_ * PPIX_ * 256];
__device__ __align__(16) __half g_xqh[(size_t)T_ * PPIX_ * 256], g_xql[(size_t)T_ * PPIX_ * 256];
__device__ __align__(16) __half g_xsh[(size_t)T_ * PPIX_ * 256], g_xsl[(size_t)T_ * PPIX_ * 256];
__device__ __align__(16) __half g_wv[9 * 256 * 256];
__device__ __align__(16) __half g_wp[9 * 512 * 256];   // off+attn fused
__device__ __align__(16) __half g_wu[9 * 256 * 256];
__device__ __align__(16) __half g_value[(size_t)T_ * HEADS_ * HW_ * 32];   // [t][head][pix][dh]
__device__ float g_off  [(size_t)T_ * 320 * HW_];
__device__ float g_attn [(size_t)T_ * 160 * HW_];
__device__ float g_adds [(size_t)4 * 5 * 2 * HW_];

// ================= merged input prep: transpose + split + border zeroing =================
// grid (65, 5, 2). z=0: input_flatten -> (g_xfh, g_xfl) [+ borders of xf AND xs]
//                  z=1: query -> g_xqh ONLY (fused conv is single-term; lo unused)
__global__ void __launch_bounds__(128) prep_x_all_kernel(
    const float* __restrict__ src0, const float* __restrict__ src1)
{
    const int t = blockIdx.y, z = blockIdx.z, tid = threadIdx.x;
    __half* dh = z ? g_xqh : g_xfh;
    __half* dl = z ? g_xql : g_xfl;

    if (blockIdx.x == 64) {   // border zeroing for this t
        for (int pp = tid; pp < PPIX_; pp += 128) {
            int py = pp / PW_, px = pp - py * PW_;
            if (py == 0 || py == PH_ - 1 || px == 0 || px == PW_ - 1) {
                size_t o = ((size_t)t * PPIX_ + pp) * 256;   // half elements
                uint4 z4 = make_uint4(0, 0, 0, 0);
#pragma unroll
                for (int c = 0; c < 32; c++) {
                    *(uint4*)((char*)dh + (o + c * 8) * 2) = z4;
                    if (z == 0) {
                        *(uint4*)((char*)dl  + (o + c * 8) * 2) = z4;
                        *(uint4*)((char*)g_xsh + (o + c * 8) * 2) = z4;
                        *(uint4*)((char*)g_xsl + (o + c * 8) * 2) = z4;
                    }
                }
            }
        }
        return;
    }

    const float* src = z ? src1 : src0;
    const int y = blockIdx.x;
    __shared__ float s[64][97];
    for (int cib = 0; cib < 4; cib++) {
        __syncthreads();
        for (int i = tid; i < 64 * 96; i += 128) {
            int r = i / 96, c = i - r * 96;
            s[r][c] = src[((size_t)(t * 256 + cib * 64 + r)) * HW_ + y * 96 + c];
        }
        __syncthreads();
        if (tid < 96) {
            size_t ob = ((size_t)t * PPIX_ + (size_t)(y + 1) * PW_ + tid + 1) * 256 + cib * 64;
#pragma unroll 8
            for (int ci = 0; ci < 64; ci++) {
                float v = s[ci][tid];
                __half h = __float2half(v);
                dh[ob + ci] = h;
                if (z == 0) dl[ob + ci] = __float2half(v - __half2float(h));
            }
        }
    }
}

// ================= merged weight prep =================
__global__ void prep_w_all_kernel(
    const float* __restrict__ w_val, const float* __restrict__ w_off,
    const float* __restrict__ w_attn, const float* __restrict__ w_out)
{
    int idx = blockIdx.x * 256 + threadIdx.x;
    if (idx >= 9 * 1024 * 256) return;
    int ci = idx & 255;
    int rest = idx >> 8;
    int co_all = rest & 1023;
    int shift = rest >> 10;
    if (co_all < 256) {
        g_wv[((size_t)(shift * 256 + co_all)) * 256 + ci] =
            __float2half(w_val[((size_t)co_all * 256 + ci) * 9 + shift]);
    } else if (co_all < 768) {
        int c2 = co_all - 256;
        float v = (c2 < 320) ? w_off[((size_t)c2 * 256 + ci) * 9 + shift]
                             : w_attn[((size_t)(c2 - 320) * 256 + ci) * 9 + shift];
        g_wp[((size_t)(shift * 512 + c2)) * 256 + ci] = __float2half(v);
    } else {
        int c3 = co_all - 768;
        g_wu[((size_t)(shift * 256 + c3)) * 256 + ci] =
            __float2half(w_out[((size_t)c3 * 256 + ci) * 9 + shift]);
    }
}

// ================= HMMA implicit-GEMM 3x3 conv (128co x 128pix, occ 2) =================
#define BROWS  330
#define BBYTES (BROWS * 128)            // 42240
#define BH_OFF 0
#define BL_OFF BBYTES                   // 42240
#define A_OFF  (2 * BBYTES)             // 84480 (128B aligned)
#define SMTOT  (2 * BBYTES + 16384)     // 100864

__device__ __forceinline__ void conv_body(char* smem,
    const __half* __restrict__ wgt,
    const __half* __restrict__ xh, const __half* __restrict__ xl,
    const float* __restrict__ bias1, const float* __restrict__ bias2,
    float* __restrict__ out, int Cout1, int CoPad, int layout, int co0, int terms)
{
    const uint32_t sb = smem_u32(smem);
    const int tid = threadIdx.x, wid = tid >> 5, lane = tid & 31;
    const int warp_m = wid & 3, warp_n = wid >> 2;
    const int t = blockIdx.z, o0 = blockIdx.y << 7;
    const int pmin = o0 + 2 * (o0 / 96);

    float C[2][8][4];
#pragma unroll
    for (int m = 0; m < 2; m++)
#pragma unroll
        for (int n = 0; n < 8; n++)
#pragma unroll
            for (int k = 0; k < 4; k++) C[m][n][k] = 0.f;

    const int kh_b = (lane >> 3) & 1;
    const int kh_a = lane >> 4;
    int prow[4];
#pragma unroll
    for (int j = 0; j < 4; j++) {
        int nl = warp_n * 64 + j * 16 + ((lane >> 4) << 3) + (lane & 7);
        int o = o0 + nl;
        prow[j] = o + 2 * (o / 96) + 99 - pmin;
    }
    int arow[2];
#pragma unroll
    for (int m = 0; m < 2; m++) arow[m] = warp_m * 32 + m * 16 + (lane & 15);

    const int ac = tid & 7;
    uint32_t adof[4];
#pragma unroll
    for (int i = 0; i < 4; i++) {
        int ar = (tid >> 3) + i * 32;
        adof[i] = ar * 128 + ((ac ^ (ar & 7)) << 4);
    }

    auto fetch_A = [&](int cs, uint4* regs) {
        const int chunk = cs / 9, shift = cs - chunk * 9;
#pragma unroll
        for (int i = 0; i < 4; i++) {
            int row = (tid >> 3) + i * 32;
            regs[i] = *(const uint4*)((const char*)wgt +
                (((size_t)(shift * CoPad + co0 + row)) * 256 + chunk * 64) * 2 + ac * 16);
        }
    };
    auto store_A = [&](const uint4* regs) {
#pragma unroll
        for (int i = 0; i < 4; i++)
            *(uint4*)(smem + A_OFF + adof[i]) = regs[i];
    };
    auto load_B = [&](int chunk) {
        const int prem = PPIX_ - pmin;
        const char* bh = (const char*)xh + (((size_t)t * PPIX_ + pmin) * 256 + chunk * 64) * 2;
        const char* bl = (const char*)xl + (((size_t)t * PPIX_ + pmin) * 256 + chunk * 64) * 2;
#pragma unroll
        for (int i = 0; i < 11; i++) {
            int idx = tid + i * 256;
            if (idx < BROWS * 8) {
                int r = idx >> 3, c = idx & 7;
                uint32_t dof = r * 128 + ((c ^ (r & 7)) << 4);
                int ok = (r < prem);
                int rs = ok ? r : 0;
                cp16(sb + BH_OFF + dof, bh + (size_t)rs * 512 + c * 16, ok);
                if (terms == 2)
                    cp16(sb + BL_OFF + dof, bl + (size_t)rs * 512 + c * 16, ok);
            }
        }
    };

    // prologue
    load_B(0);
    {
        uint4 a0[4];
        fetch_A(0, a0);
        store_A(a0);
    }
    cp_async_wait_all();
    __syncthreads();

    for (int cs = 0; cs < 36; cs++) {
        const int shift = cs % 9;
        uint4 apre[4];
        if (cs + 1 < 36) fetch_A(cs + 1, apre);

        const uint32_t AS = sb + A_OFF;
        const int off = (shift / 3 - 1) * PW_ + (shift % 3 - 1);
#pragma unroll
        for (int ks = 0; ks < 4; ks++) {
            uint32_t a[2][4], b[4][4];
#pragma unroll
            for (int m = 0; m < 2; m++) {
                int c = ks * 2 + kh_a;
                ldsm4(a[m], AS + arow[m] * 128 + ((c ^ (arow[m] & 7)) << 4));
            }
            if (terms == 2) {
                // W * Xl
#pragma unroll
                for (int j = 0; j < 4; j++) {
                    int r = prow[j] + off;
                    int c = ks * 2 + kh_b;
                    ldsm4(b[j], sb + BL_OFF + r * 128 + ((c ^ (r & 7)) << 4));
                }
#pragma unroll
                for (int m = 0; m < 2; m++)
#pragma unroll
                    for (int n = 0; n < 8; n++)
                        mma16816(C[m][n], a[m], b[n >> 1][(n & 1) * 2], b[n >> 1][(n & 1) * 2 + 1]);
            }
            // W * Xh
#pragma unroll
            for (int j = 0; j < 4; j++) {
                int r = prow[j] + off;
                int c = ks * 2 + kh_b;
                ldsm4(b[j], sb + BH_OFF + r * 128 + ((c ^ (r & 7)) << 4));
            }
#pragma unroll
            for (int m = 0; m < 2; m++)
#pragma unroll
                for (int n = 0; n < 8; n++)
                    mma16816(C[m][n], a[m], b[n >> 1][(n & 1) * 2], b[n >> 1][(n & 1) * 2 + 1]);
        }

        __syncthreads();
        if (cs + 1 < 36) store_A(apre);
        if (shift == 8 && cs + 1 < 36) {
            load_B(cs / 9 + 1);
            cp_async_wait_all();
        }
        __syncthreads();
    }

    // epilogue
#pragma unroll
    for (int m = 0; m < 2; m++) {
        const int coA = co0 + warp_m * 32 + m * 16 + (lane >> 2);
#pragma unroll
        for (int n = 0; n < 8; n++) {
            const int px = o0 + warp_n * 64 + n * 8 + ((lane & 3) << 1);
#pragma unroll
            for (int half = 0; half < 2; half++) {
                const int co = coA + half * 8;
                const float v0 = C[m][n][half * 2 + 0];
                const float v1 = C[m][n][half * 2 + 1];
                if (layout == 0) {
                    const float bv = bias1[co];
                    float* op = out + ((size_t)t * Cout1 + co) * HW_ + px;
                    op[0] = v0 + bv; op[1] = v1 + bv;
                } else if (layout == 1) {
                    const float bv = bias1[co];
                    const int head = co >> 5, dh = co & 31;
                    __half* op = g_value + (((size_t)(t * 8 + head) * HW_ + px) << 5) + dh;
                    op[0]  = __float2half(v0 + bv);
                    op[32] = __float2half(v1 + bv);
                } else {
                    if (co < 480) {
                        float bv; float* op;
                        if (co < 320) { bv = bias1[co];       op = g_off  + ((size_t)t * 320 + co)       * HW_ + px; }
                        else          { bv = bias2[co - 320]; op = g_attn + ((size_t)t * 160 + co - 320) * HW_ + px; }
                        op[0] = v0 + bv; op[1] = v1 + bv;
                    }
                }
            }
        }
    }
}

// merged value(x<2, 2-term) + off/attn(x>=2, single-term) conv
__global__ void __launch_bounds__(256, 2) conv_main_kernel(
    const float* __restrict__ b_val, const float* __restrict__ b_off, const float* __restrict__ b_attn)
{
    extern __shared__ char smem[];
    if (blockIdx.x < 2)
        conv_body(smem, g_wv, g_xfh, g_xfl, b_val, nullptr, nullptr, 256, 256, 1, (int)blockIdx.x << 7, 2);
    else
        conv_body(smem, g_wp, g_xqh, g_xqh, b_off, b_attn, nullptr, 320, 512, 2, ((int)blockIdx.x - 2) << 7, 1);
}

__global__ void __launch_bounds__(256, 2) conv_out_kernel(
    const float* __restrict__ b_out, float* __restrict__ out)
{
    extern __shared__ char smem[];
    conv_body(smem, g_wu, g_xsh, g_xsl, b_out, nullptr, out, 256, 256, 0, (int)blockIdx.x << 7, 2);
}

// ================= fused flow composition (single block) =================
__constant__ int c_flow_steps[9][3] = {
    {1,  7,  2},   // f02
    {2, 13,  3},   // f03
    {3, 19,  4},   // f04
    {7, 13,  8},   // f13
    {8, 19,  9},   // f14
    {13, 19, 14},  // f24
    {11, 5, 10},   // b20
    {17, 11, 16},  // b31
    {16, 5, 15},   // b30
};

__global__ void __launch_bounds__(1024) flow_all_kernel(
    const float* __restrict__ ff, const float* __restrict__ fb)
{
    const int tid = threadIdx.x;
    for (int p = tid; p < HW_; p += 1024) {
#pragma unroll
        for (int i = 0; i < 4; i++)
#pragma unroll
            for (int j = 0; j < 5; j++) {
                g_adds[((i * 5 + j) * 2 + 0) * HW_ + p] = 0.f;
                g_adds[((i * 5 + j) * 2 + 1) * HW_ + p] = 0.f;
            }
#pragma unroll
        for (int k = 0; k < 4; k++) {
            g_adds[((k * 5 + (k + 1)) * 2 + 0) * HW_ + p] = ff[(k * 2 + 0) * HW_ + p];
            g_adds[((k * 5 + (k + 1)) * 2 + 1) * HW_ + p] = ff[(k * 2 + 1) * HW_ + p];
        }
#pragma unroll
        for (int k = 0; k < 3; k++) {
            g_adds[(((k + 1) * 5 + k) * 2 + 0) * HW_ + p] = fb[(k * 2 + 0) * HW_ + p];
            g_adds[(((k + 1) * 5 + k) * 2 + 1) * HW_ + p] = fb[(k * 2 + 1) * HW_ + p];
        }
    }
    __syncthreads();
    for (int step = 0; step < 9; step++) {
        const float* bptr = g_adds + c_flow_steps[step][0] * 2 * HW_;
        const float* tgt  = g_adds + c_flow_steps[step][1] * 2 * HW_;
        float*       dst  = g_adds + c_flow_steps[step][2] * 2 * HW_;
        for (int p = tid; p < HW_; p += 1024) {
            int y = p / W_, x = p - y * W_;
            float fx = bptr[p], fy = bptr[HW_ + p];
            float px = (float)x + fx, py = (float)y + fy;
            float x0f = floorf(px), y0f = floorf(py);
            int   x0 = (int)x0f, y0 = (int)y0f;
            float wx1 = px - x0f, wx0 = 1.f - wx1;
            float wy1 = py - y0f, wy0 = 1.f - wy1;
            float s0 = 0.f, s1 = 0.f;
            const int xs[4] = {x0, x0 + 1, x0, x0 + 1};
            const int ys[4] = {y0, y0, y0 + 1, y0 + 1};
            const float ws[4] = {wx0 * wy0, wx1 * wy0, wx0 * wy1, wx1 * wy1};
#pragma unroll
            for (int k = 0; k < 4; k++) {
                if ((unsigned)xs[k] < W_ && (unsigned)ys[k] < H_) {
                    int idx = ys[k] * W_ + xs[k];
                    s0 = fmaf(tgt[idx], ws[k], s0);
                    s1 = fmaf(tgt[HW_ + idx], ws[k], s1);
                }
            }
            dst[p]       = fx + s0;
            dst[HW_ + p] = fy + s1;
        }
        __syncthreads();
    }
}

// ================= deformable sampling (fp16 value cache) =================
__global__ void __launch_bounds__(256) sample_kernel(const float* __restrict__ ref_pts)
{
    const int item = blockIdx.x * 8 + (threadIdx.x >> 5);
    const int lane = threadIdx.x & 31;
    const int head = item & 7;
    const int q    = item >> 3;
    const int t    = q / HW_;
    const int p    = q - t * HW_;
    const int ri   = (t == 4) ? 3 : t;

    const float* attn_base = g_attn + (size_t)t * 160 * HW_ + (size_t)head * 20 * HW_ + p;
    float lg[20];
    float mx = -1e30f;
#pragma unroll
    for (int i = 0; i < 20; i++) { lg[i] = attn_base[(size_t)i * HW_]; mx = fmaxf(mx, lg[i]); }
    float ssum = 0.f;
#pragma unroll
    for (int i = 0; i < 20; i++) { lg[i] = __expf(lg[i] - mx); ssum += lg[i]; }
    const float inv = 1.f / ssum;

    const float* off_base = g_off + (size_t)t * 320 * HW_ + p;
    float outv = 0.f;
#pragma unroll
    for (int l = 0; l < LVLS_; l++) {
        const float ax = g_adds[((ri * 5 + l) * 2 + 0) * HW_ + p];
        const float ay = g_adds[((ri * 5 + l) * 2 + 1) * HW_ + p];
        const float rx = ref_pts[((size_t)q * 5 + l) * 2 + 0];
        const float ry = ref_pts[((size_t)q * 5 + l) * 2 + 1];
        const __half* vimg = g_value + ((size_t)(l * 8 + head) * HW_ << 5) + lane;
#pragma unroll
        for (int pt = 0; pt < PTS_; pt++) {
            const int ch = ((head * 5 + l) * 4 + pt) * 2;
            const float ox = off_base[(size_t)ch * HW_] + ax;
            const float oy = off_base[(size_t)(ch + 1) * HW_] + ay;
            const float px = fmaf(rx, (float)W_, ox) - 0.5f;
            const float py = fmaf(ry, (float)H_, oy) - 0.5f;
            const float x0f = floorf(px), y0f = floorf(py);
            const int   x0 = (int)x0f, y0 = (int)y0f;
            const float wx1 = px - x0f, wx0 = 1.f - wx1;
            const float wy1 = py - y0f, wy0 = 1.f - wy1;
            float s = 0.f;
            const bool vx0 = (unsigned)x0 < W_,       vx1 = (unsigned)(x0 + 1) < W_;
            const bool vy0 = (unsigned)y0 < H_,       vy1 = (unsigned)(y0 + 1) < H_;
            if (vy0) {
                const long long r0 = (long long)y0 * W_;
                if (vx0) s = fmaf(__half2float(vimg[(r0 + x0) << 5]),     wx0 * wy0, s);
                if (vx1) s = fmaf(__half2float(vimg[(r0 + x0 + 1) << 5]), wx1 * wy0, s);
            }
            if (vy1) {
                const long long r1 = (long long)(y0 + 1) * W_;
                if (vx0) s = fmaf(__half2float(vimg[(r1 + x0) << 5]),     wx0 * wy1, s);
                if (vx1) s = fmaf(__half2float(vimg[(r1 + x0 + 1) << 5]), wx1 * wy1, s);
            }
            outv = fmaf(s, lg[l * 4 + pt] * inv, outv);
        }
    }
    const int y = p / 96, x = p - y * 96;
    const size_t ob = ((size_t)t * PPIX_ + (size_t)(y + 1) * PW_ + x + 1) * 256 + (head << 5) + lane;
    __half h = __float2half(outv);
    g_xsh[ob] = h;
    g_xsl[ob] = __float2half(outv - __half2float(h));
}

// ================= launch =================
extern "C" void kernel_launch(void* const* d_in, const int* in_sizes, int n_in,
                              void* d_out, int out_size)
{
    (void)in_sizes; (void)n_in; (void)out_size;
    const float* query         = (const float*)d_in[0];
    const float* input_flatten = (const float*)d_in[1];
    const float* ref_pts       = (const float*)d_in[2];
    const float* ff     = (const float*)d_in[6];
    const float* fb     = (const float*)d_in[7];
    const float* w_off  = (const float*)d_in[8];
    const float* b_off  = (const float*)d_in[9];
    const float* w_attn = (const float*)d_in[10];
    const float* b_attn = (const float*)d_in[11];
    const float* w_val  = (const float*)d_in[12];
    const float* b_val  = (const float*)d_in[13];
    const float* w_out  = (const float*)d_in[14];
    const float* b_out  = (const float*)d_in[15];
    float* out = (float*)d_out;

    cudaFuncSetAttribute(conv_main_kernel, cudaFuncAttributeMaxDynamicSharedMemorySize, SMTOT);
    cudaFuncSetAttribute(conv_out_kernel,  cudaFuncAttributeMaxDynamicSharedMemorySize, SMTOT);

    // 0: merged input prep
    prep_x_all_kernel<<<dim3(65, 5, 2), 128>>>(input_flatten, query);
    // 1: merged weight prep
    prep_w_all_kernel<<<(9 * 1024 * 256 + 255) / 256, 256>>>(w_val, w_off, w_attn, w_out);
    // 2: flow composition
    flow_all_kernel<<<1, 1024>>>(ff, fb);
    // 3: merged value(2-term) + off/attn(1-term) convs
    conv_main_kernel<<<dim3(6, 48, 5), 256, SMTOT>>>(b_val, b_off, b_attn);
    // 4: deformable attention sampling
    sample_kernel<<<(T_ * HW_ * HEADS_) / 8, 256>>>(ref_pts);
    // 5: output projection (2-term)
    conv_out_kernel<<<dim3(2, 48, 5), 256, SMTOT>>>(b_out, out);
}

// round 12
// speedup vs baseline: 1.2564x; 1.2564x over previous
#include <cuda_runtime.h>
#include <cuda_fp16.h>
#include <cstdint>
#include <math.h>

#define T_ 5
#define H_ 64
#define W_ 96
#define HW_ (H_ * W_)
#define HEADS_ 8
#define LVLS_ 5
#define PTS_ 4
#define PW_ (W_ + 2)            // 98
#define PH_ (H_ + 2)            // 66
#define PPIX_ (PW_ * PH_)       // 6468

// ================= helpers =================
__device__ __forceinline__ uint32_t smem_u32(const void* p) {
    uint32_t a;
    asm("{ .reg .u64 t; cvta.to.shared.u64 t, %1; cvt.u32.u64 %0, t; }" : "=r"(a) : "l"(p));
    return a;
}
__device__ __forceinline__ void ldsm4(uint32_t* r, uint32_t addr) {
    asm volatile("ldmatrix.sync.aligned.m8n8.x4.shared.b16 {%0,%1,%2,%3}, [%4];"
        : "=r"(r[0]), "=r"(r[1]), "=r"(r[2]), "=r"(r[3]) : "r"(addr));
}
__device__ __forceinline__ void mma16816(float* c, const uint32_t* a, uint32_t b0, uint32_t b1) {
    asm volatile(
        "mma.sync.aligned.m16n8k16.row.col.f32.f16.f16.f32 "
        "{%0,%1,%2,%3}, {%4,%5,%6,%7}, {%8,%9}, {%0,%1,%2,%3};"
        : "+f"(c[0]), "+f"(c[1]), "+f"(c[2]), "+f"(c[3])
        : "r"(a[0]), "r"(a[1]), "r"(a[2]), "r"(a[3]), "r"(b0), "r"(b1));
}
__device__ __forceinline__ void cp16(uint32_t dst, const void* src, int ok) {
    asm volatile(
        "{\n\t.reg .pred p;\n\tsetp.ne.s32 p, %2, 0;\n\t"
        "@p cp.async.cg.shared.global [%0], [%1], 16;\n\t"
        "@!p cp.async.cg.shared.global [%0], [%1], 16, 0;\n\t}"
        :: "r"(dst), "l"(src), "r"(ok) : "memory");
}
__device__ __forceinline__ void cp_async_wait_all() {
    asm volatile("cp.async.commit_group;\ncp.async.wait_group 0;" ::: "memory");
}

// ================= scratch =================
__device__ __align__(16) __half g_xfh[(size_t)T_ * PPIX_ * 256];
__device__ __align__(16) __half g_xqh[(size_t)T_ * PPIX_ * 256];
__device__ __align__(16) __half g_xsh[(size_t)T_ * PPIX_ * 256], g_xsl[(size_t)T_ * PPIX_ * 256];
__device__ __align__(16) __half g_wv[9 * 256 * 256];
__device__ __align__(16) __half g_wp[9 * 512 * 256];   // off+attn fused
__device__ __align__(16) __half g_wu[9 * 256 * 256];
__device__ __align__(16) __half g_value[(size_t)T_ * HEADS_ * HW_ * 32];   // [t][head][pix][dh]
__device__ float g_off  [(size_t)T_ * 320 * HW_];
__device__ float g_attn [(size_t)T_ * 160 * HW_];
__device__ float g_adds [(size_t)4 * 5 * 2 * HW_];

// ================= merged input prep =================
// grid (65, 5, 2). z=0: input_flatten -> g_xfh [+ borders of xf AND xs pair]
//                  z=1: query -> g_xqh
__global__ void __launch_bounds__(128) prep_x_all_kernel(
    const float* __restrict__ src0, const float* __restrict__ src1)
{
    const int t = blockIdx.y, z = blockIdx.z, tid = threadIdx.x;
    __half* dh = z ? g_xqh : g_xfh;

    if (blockIdx.x == 64) {
        for (int pp = tid; pp < PPIX_; pp += 128) {
            int py = pp / PW_, px = pp - py * PW_;
            if (py == 0 || py == PH_ - 1 || px == 0 || px == PW_ - 1) {
                size_t o = ((size_t)t * PPIX_ + pp) * 256;
                uint4 z4 = make_uint4(0, 0, 0, 0);
#pragma unroll
                for (int c = 0; c < 32; c++) {
                    *(uint4*)((char*)dh + (o + c * 8) * 2) = z4;
                    if (z == 0) {
                        *(uint4*)((char*)g_xsh + (o + c * 8) * 2) = z4;
                        *(uint4*)((char*)g_xsl + (o + c * 8) * 2) = z4;
                    }
                }
            }
        }
        return;
    }

    const float* src = z ? src1 : src0;
    const int y = blockIdx.x;
    __shared__ float s[64][97];
    for (int cib = 0; cib < 4; cib++) {
        __syncthreads();
        for (int i = tid; i < 64 * 96; i += 128) {
            int r = i / 96, c = i - r * 96;
            s[r][c] = src[((size_t)(t * 256 + cib * 64 + r)) * HW_ + y * 96 + c];
        }
        __syncthreads();
        if (tid < 96) {
            size_t ob = ((size_t)t * PPIX_ + (size_t)(y + 1) * PW_ + tid + 1) * 256 + cib * 64;
#pragma unroll 8
            for (int ci = 0; ci < 64; ci++)
                dh[ob + ci] = __float2half(s[ci][tid]);
        }
    }
}

// ================= merged weight prep =================
__global__ void prep_w_all_kernel(
    const float* __restrict__ w_val, const float* __restrict__ w_off,
    const float* __restrict__ w_attn, const float* __restrict__ w_out)
{
    int idx = blockIdx.x * 256 + threadIdx.x;
    if (idx >= 9 * 1024 * 256) return;
    int ci = idx & 255;
    int rest = idx >> 8;
    int co_all = rest & 1023;
    int shift = rest >> 10;
    if (co_all < 256) {
        g_wv[((size_t)(shift * 256 + co_all)) * 256 + ci] =
            __float2half(w_val[((size_t)co_all * 256 + ci) * 9 + shift]);
    } else if (co_all < 768) {
        int c2 = co_all - 256;
        float v = (c2 < 320) ? w_off[((size_t)c2 * 256 + ci) * 9 + shift]
                             : w_attn[((size_t)(c2 - 320) * 256 + ci) * 9 + shift];
        g_wp[((size_t)(shift * 512 + c2)) * 256 + ci] = __float2half(v);
    } else {
        int c3 = co_all - 768;
        g_wu[((size_t)(shift * 256 + c3)) * 256 + ci] =
            __float2half(w_out[((size_t)c3 * 256 + ci) * 9 + shift]);
    }
}

// ================= conv common pieces =================
#define BROWS  330
#define BBYTES (BROWS * 128)            // 42240

// --- 1-term body: B hi only, A double-buffered, 1 sync/iter ---
#define M_A_OFF  BBYTES                 // 42240
#define SMTOT_M  (BBYTES + 32768)       // 75008

__device__ __forceinline__ void conv_body1(char* smem,
    const __half* __restrict__ wgt, const __half* __restrict__ xh,
    const float* __restrict__ bias1, const float* __restrict__ bias2,
    int CoPad, int layout, int co0)
{
    const uint32_t sb = smem_u32(smem);
    const int tid = threadIdx.x, wid = tid >> 5, lane = tid & 31;
    const int warp_m = wid & 3, warp_n = wid >> 2;
    const int t = blockIdx.z, o0 = blockIdx.y << 7;
    const int pmin = o0 + 2 * (o0 / 96);

    float C[2][8][4];
#pragma unroll
    for (int m = 0; m < 2; m++)
#pragma unroll
        for (int n = 0; n < 8; n++)
#pragma unroll
            for (int k = 0; k < 4; k++) C[m][n][k] = 0.f;

    const int kh_b = (lane >> 3) & 1;
    const int kh_a = lane >> 4;
    int prow[4];
#pragma unroll
    for (int j = 0; j < 4; j++) {
        int nl = warp_n * 64 + j * 16 + ((lane >> 4) << 3) + (lane & 7);
        int o = o0 + nl;
        prow[j] = o + 2 * (o / 96) + 99 - pmin;
    }
    int arow[2];
#pragma unroll
    for (int m = 0; m < 2; m++) arow[m] = warp_m * 32 + m * 16 + (lane & 15);

    const int ac = tid & 7;
    uint32_t adof[4];
#pragma unroll
    for (int i = 0; i < 4; i++) {
        int ar = (tid >> 3) + i * 32;
        adof[i] = ar * 128 + ((ac ^ (ar & 7)) << 4);
    }

    auto fetch_A = [&](int cs, uint4* regs) {
        const int chunk = cs / 9, shift = cs - chunk * 9;
#pragma unroll
        for (int i = 0; i < 4; i++) {
            int row = (tid >> 3) + i * 32;
            regs[i] = *(const uint4*)((const char*)wgt +
                (((size_t)(shift * CoPad + co0 + row)) * 256 + chunk * 64) * 2 + ac * 16);
        }
    };
    auto store_A = [&](int buf, const uint4* regs) {
        char* st = smem + M_A_OFF + buf * 16384;
#pragma unroll
        for (int i = 0; i < 4; i++)
            *(uint4*)(st + adof[i]) = regs[i];
    };
    auto load_B = [&](int chunk) {
        const int prem = PPIX_ - pmin;
        const char* bh = (const char*)xh + (((size_t)t * PPIX_ + pmin) * 256 + chunk * 64) * 2;
#pragma unroll
        for (int i = 0; i < 11; i++) {
            int idx = tid + i * 256;
            if (idx < BROWS * 8) {
                int r = idx >> 3, c = idx & 7;
                uint32_t dof = r * 128 + ((c ^ (r & 7)) << 4);
                int ok = (r < prem);
                int rs = ok ? r : 0;
                cp16(sb + dof, bh + (size_t)rs * 512 + c * 16, ok);
            }
        }
    };

    load_B(0);
    {
        uint4 a0[4];
        fetch_A(0, a0);
        store_A(0, a0);
    }
    cp_async_wait_all();
    __syncthreads();

    for (int cs = 0; cs < 36; cs++) {
        const int shift = cs % 9;
        uint4 apre[4];
        if (cs + 1 < 36) fetch_A(cs + 1, apre);

        const uint32_t AS = sb + M_A_OFF + (cs & 1) * 16384;
        const int off = (shift / 3 - 1) * PW_ + (shift % 3 - 1);
#pragma unroll
        for (int ks = 0; ks < 4; ks++) {
            uint32_t a[2][4], b[4][4];
#pragma unroll
            for (int m = 0; m < 2; m++) {
                int c = ks * 2 + kh_a;
                ldsm4(a[m], AS + arow[m] * 128 + ((c ^ (arow[m] & 7)) << 4));
            }
#pragma unroll
            for (int j = 0; j < 4; j++) {
                int r = prow[j] + off;
                int c = ks * 2 + kh_b;
                ldsm4(b[j], sb + r * 128 + ((c ^ (r & 7)) << 4));
            }
#pragma unroll
            for (int m = 0; m < 2; m++)
#pragma unroll
                for (int n = 0; n < 8; n++)
                    mma16816(C[m][n], a[m], b[n >> 1][(n & 1) * 2], b[n >> 1][(n & 1) * 2 + 1]);
        }

        // store next A into the OTHER buffer (its readers finished at end of cs-1)
        if (cs + 1 < 36) store_A((cs + 1) & 1, apre);
        if (shift == 8 && cs + 1 < 36) {
            __syncthreads();              // all B reads of this chunk done
            load_B(cs / 9 + 1);
            cp_async_wait_all();
        }
        __syncthreads();                  // publish A (and B at boundaries)
    }

    // epilogue
#pragma unroll
    for (int m = 0; m < 2; m++) {
        const int coA = co0 + warp_m * 32 + m * 16 + (lane >> 2);
#pragma unroll
        for (int n = 0; n < 8; n++) {
            const int px = o0 + warp_n * 64 + n * 8 + ((lane & 3) << 1);
#pragma unroll
            for (int half = 0; half < 2; half++) {
                const int co = coA + half * 8;
                const float v0 = C[m][n][half * 2 + 0];
                const float v1 = C[m][n][half * 2 + 1];
                if (layout == 1) {
                    const float bv = bias1[co];
                    const int head = co >> 5, dh = co & 31;
                    __half* op = g_value + (((size_t)(t * 8 + head) * HW_ + px) << 5) + dh;
                    op[0]  = __float2half(v0 + bv);
                    op[32] = __float2half(v1 + bv);
                } else {
                    if (co < 480) {
                        float bv; float* op;
                        if (co < 320) { bv = bias1[co];       op = g_off  + ((size_t)t * 320 + co)       * HW_ + px; }
                        else          { bv = bias2[co - 320]; op = g_attn + ((size_t)t * 160 + co - 320) * HW_ + px; }
                        op[0] = v0 + bv; op[1] = v1 + bv;
                    }
                }
            }
        }
    }
}

__global__ void __launch_bounds__(256, 2) conv_main_kernel(
    const float* __restrict__ b_val, const float* __restrict__ b_off, const float* __restrict__ b_attn)
{
    extern __shared__ char smem[];
    if (blockIdx.x < 2)
        conv_body1(smem, g_wv, g_xfh, b_val, nullptr, 256, 1, (int)blockIdx.x << 7);
    else
        conv_body1(smem, g_wp, g_xqh, b_off, b_attn, 512, 2, ((int)blockIdx.x - 2) << 7);
}

// --- 2-term body (out conv): BH+BL, single A stage, 2 syncs/iter ---
#define O_A_OFF  (2 * BBYTES)           // 84480
#define SMTOT_O  (2 * BBYTES + 16384)   // 100864

__global__ void __launch_bounds__(256, 2) conv_out_kernel(
    const float* __restrict__ b_out, float* __restrict__ out)
{
    extern __shared__ char smem[];
    const uint32_t sb = smem_u32(smem);
    const int tid = threadIdx.x, wid = tid >> 5, lane = tid & 31;
    const int warp_m = wid & 3, warp_n = wid >> 2;
    const int t = blockIdx.z, o0 = blockIdx.y << 7, co0 = (int)blockIdx.x << 7;
    const int pmin = o0 + 2 * (o0 / 96);

    float C[2][8][4];
#pragma unroll
    for (int m = 0; m < 2; m++)
#pragma unroll
        for (int n = 0; n < 8; n++)
#pragma unroll
            for (int k = 0; k < 4; k++) C[m][n][k] = 0.f;

    const int kh_b = (lane >> 3) & 1;
    const int kh_a = lane >> 4;
    int prow[4];
#pragma unroll
    for (int j = 0; j < 4; j++) {
        int nl = warp_n * 64 + j * 16 + ((lane >> 4) << 3) + (lane & 7);
        int o = o0 + nl;
        prow[j] = o + 2 * (o / 96) + 99 - pmin;
    }
    int arow[2];
#pragma unroll
    for (int m = 0; m < 2; m++) arow[m] = warp_m * 32 + m * 16 + (lane & 15);

    const int ac = tid & 7;
    uint32_t adof[4];
#pragma unroll
    for (int i = 0; i < 4; i++) {
        int ar = (tid >> 3) + i * 32;
        adof[i] = ar * 128 + ((ac ^ (ar & 7)) << 4);
    }

    auto fetch_A = [&](int cs, uint4* regs) {
        const int chunk = cs / 9, shift = cs - chunk * 9;
#pragma unroll
        for (int i = 0; i < 4; i++) {
            int row = (tid >> 3) + i * 32;
            regs[i] = *(const uint4*)((const char*)g_wu +
                (((size_t)(shift * 256 + co0 + row)) * 256 + chunk * 64) * 2 + ac * 16);
        }
    };
    auto store_A = [&](const uint4* regs) {
#pragma unroll
        for (int i = 0; i < 4; i++)
            *(uint4*)(smem + O_A_OFF + adof[i]) = regs[i];
    };
    auto load_B = [&](int chunk) {
        const int prem = PPIX_ - pmin;
        const char* bh = (const char*)g_xsh + (((size_t)t * PPIX_ + pmin) * 256 + chunk * 64) * 2;
        const char* bl = (const char*)g_xsl + (((size_t)t * PPIX_ + pmin) * 256 + chunk * 64) * 2;
#pragma unroll
        for (int i = 0; i < 11; i++) {
            int idx = tid + i * 256;
            if (idx < BROWS * 8) {
                int r = idx >> 3, c = idx & 7;
                uint32_t dof = r * 128 + ((c ^ (r & 7)) << 4);
                int ok = (r < prem);
                int rs = ok ? r : 0;
                cp16(sb + dof,          bh + (size_t)rs * 512 + c * 16, ok);
                cp16(sb + BBYTES + dof, bl + (size_t)rs * 512 + c * 16, ok);
            }
        }
    };

    load_B(0);
    {
        uint4 a0[4];
        fetch_A(0, a0);
        store_A(a0);
    }
    cp_async_wait_all();
    __syncthreads();

    for (int cs = 0; cs < 36; cs++) {
        const int shift = cs % 9;
        uint4 apre[4];
        if (cs + 1 < 36) fetch_A(cs + 1, apre);

        const uint32_t AS = sb + O_A_OFF;
        const int off = (shift / 3 - 1) * PW_ + (shift % 3 - 1);
#pragma unroll
        for (int ks = 0; ks < 4; ks++) {
            uint32_t a[2][4], b[4][4];
#pragma unroll
            for (int m = 0; m < 2; m++) {
                int c = ks * 2 + kh_a;
                ldsm4(a[m], AS + arow[m] * 128 + ((c ^ (arow[m] & 7)) << 4));
            }
#pragma unroll
            for (int j = 0; j < 4; j++) {
                int r = prow[j] + off;
                int c = ks * 2 + kh_b;
                ldsm4(b[j], sb + BBYTES + r * 128 + ((c ^ (r & 7)) << 4));
            }
#pragma unroll
            for (int m = 0; m < 2; m++)
#pragma unroll
                for (int n = 0; n < 8; n++)
                    mma16816(C[m][n], a[m], b[n >> 1][(n & 1) * 2], b[n >> 1][(n & 1) * 2 + 1]);
#pragma unroll
            for (int j = 0; j < 4; j++) {
                int r = prow[j] + off;
                int c = ks * 2 + kh_b;
                ldsm4(b[j], sb + r * 128 + ((c ^ (r & 7)) << 4));
            }
#pragma unroll
            for (int m = 0; m < 2; m++)
#pragma unroll
                for (int n = 0; n < 8; n++)
                    mma16816(C[m][n], a[m], b[n >> 1][(n & 1) * 2], b[n >> 1][(n & 1) * 2 + 1]);
        }

        __syncthreads();
        if (cs + 1 < 36) store_A(apre);
        if (shift == 8 && cs + 1 < 36) {
            load_B(cs / 9 + 1);
            cp_async_wait_all();
        }
        __syncthreads();
    }

#pragma unroll
    for (int m = 0; m < 2; m++) {
        const int coA = co0 + warp_m * 32 + m * 16 + (lane >> 2);
#pragma unroll
        for (int n = 0; n < 8; n++) {
            const int px = o0 + warp_n * 64 + n * 8 + ((lane & 3) << 1);
#pragma unroll
            for (int half = 0; half < 2; half++) {
                const int co = coA + half * 8;
                const float bv = b_out[co];
                float* op = out + ((size_t)t * 256 + co) * HW_ + px;
                op[0] = C[m][n][half * 2 + 0] + bv;
                op[1] = C[m][n][half * 2 + 1] + bv;
            }
        }
    }
}

// ================= fused flow composition (single block) =================
__constant__ int c_flow_steps[9][3] = {
    {1,  7,  2},  {2, 13,  3},  {3, 19,  4},
    {7, 13,  8},  {8, 19,  9},  {13, 19, 14},
    {11, 5, 10},  {17, 11, 16}, {16, 5, 15},
};

__global__ void __launch_bounds__(1024) flow_all_kernel(
    const float* __restrict__ ff, const float* __restrict__ fb)
{
    const int tid = threadIdx.x;
    for (int p = tid; p < HW_; p += 1024) {
#pragma unroll
        for (int i = 0; i < 4; i++)
#pragma unroll
            for (int j = 0; j < 5; j++) {
                g_adds[((i * 5 + j) * 2 + 0) * HW_ + p] = 0.f;
                g_adds[((i * 5 + j) * 2 + 1) * HW_ + p] = 0.f;
            }
#pragma unroll
        for (int k = 0; k < 4; k++) {
            g_adds[((k * 5 + (k + 1)) * 2 + 0) * HW_ + p] = ff[(k * 2 + 0) * HW_ + p];
            g_adds[((k * 5 + (k + 1)) * 2 + 1) * HW_ + p] = ff[(k * 2 + 1) * HW_ + p];
        }
#pragma unroll
        for (int k = 0; k < 3; k++) {
            g_adds[(((k + 1) * 5 + k) * 2 + 0) * HW_ + p] = fb[(k * 2 + 0) * HW_ + p];
            g_adds[(((k + 1) * 5 + k) * 2 + 1) * HW_ + p] = fb[(k * 2 + 1) * HW_ + p];
        }
    }
    __syncthreads();
    for (int step = 0; step < 9; step++) {
        const float* bptr = g_adds + c_flow_steps[step][0] * 2 * HW_;
        const float* tgt  = g_adds + c_flow_steps[step][1] * 2 * HW_;
        float*       dst  = g_adds + c_flow_steps[step][2] * 2 * HW_;
        for (int p = tid; p < HW_; p += 1024) {
            int y = p / W_, x = p - y * W_;
            float fx = bptr[p], fy = bptr[HW_ + p];
            float px = (float)x + fx, py = (float)y + fy;
            float x0f = floorf(px), y0f = floorf(py);
            int   x0 = (int)x0f, y0 = (int)y0f;
            float wx1 = px - x0f, wx0 = 1.f - wx1;
            float wy1 = py - y0f, wy0 = 1.f - wy1;
            float s0 = 0.f, s1 = 0.f;
            const int xs[4] = {x0, x0 + 1, x0, x0 + 1};
            const int ys[4] = {y0, y0, y0 + 1, y0 + 1};
            const float ws[4] = {wx0 * wy0, wx1 * wy0, wx0 * wy1, wx1 * wy1};
#pragma unroll
            for (int k = 0; k < 4; k++) {
                if ((unsigned)xs[k] < W_ && (unsigned)ys[k] < H_) {
                    int idx = ys[k] * W_ + xs[k];
                    s0 = fmaf(tgt[idx], ws[k], s0);
                    s1 = fmaf(tgt[HW_ + idx], ws[k], s1);
                }
            }
            dst[p]       = fx + s0;
            dst[HW_ + p] = fy + s1;
        }
        __syncthreads();
    }
}

// ================= deformable sampling (fp16 value cache) =================
__global__ void __launch_bounds__(256) sample_kernel(const float* __restrict__ ref_pts)
{
    const int item = blockIdx.x * 8 + (threadIdx.x >> 5);
    const int lane = threadIdx.x & 31;
    const int head = item & 7;
    const int q    = item >> 3;
    const int t    = q / HW_;
    const int p    = q - t * HW_;
    const int ri   = (t == 4) ? 3 : t;

    const float* attn_base = g_attn + (size_t)t * 160 * HW_ + (size_t)head * 20 * HW_ + p;
    float lg[20];
    float mx = -1e30f;
#pragma unroll
    for (int i = 0; i < 20; i++) { lg[i] = attn_base[(size_t)i * HW_]; mx = fmaxf(mx, lg[i]); }
    float ssum = 0.f;
#pragma unroll
    for (int i = 0; i < 20; i++) { lg[i] = __expf(lg[i] - mx); ssum += lg[i]; }
    const float inv = 1.f / ssum;

    const float* off_base = g_off + (size_t)t * 320 * HW_ + p;
    float outv = 0.f;
#pragma unroll
    for (int l = 0; l < LVLS_; l++) {
        const float ax = g_adds[((ri * 5 + l) * 2 + 0) * HW_ + p];
        const float ay = g_adds[((ri * 5 + l) * 2 + 1) * HW_ + p];
        const float rx = ref_pts[((size_t)q * 5 + l) * 2 + 0];
        const float ry = ref_pts[((size_t)q * 5 + l) * 2 + 1];
        const __half* vimg = g_value + ((size_t)(l * 8 + head) * HW_ << 5) + lane;
#pragma unroll
        for (int pt = 0; pt < PTS_; pt++) {
            const int ch = ((head * 5 + l) * 4 + pt) * 2;
            const float ox = off_base[(size_t)ch * HW_] + ax;
            const float oy = off_base[(size_t)(ch + 1) * HW_] + ay;
            const float px = fmaf(rx, (float)W_, ox) - 0.5f;
            const float py = fmaf(ry, (float)H_, oy) - 0.5f;
            const float x0f = floorf(px), y0f = floorf(py);
            const int   x0 = (int)x0f, y0 = (int)y0f;
            const float wx1 = px - x0f, wx0 = 1.f - wx1;
            const float wy1 = py - y0f, wy0 = 1.f - wy1;
            float s = 0.f;
            const bool vx0 = (unsigned)x0 < W_,       vx1 = (unsigned)(x0 + 1) < W_;
            const bool vy0 = (unsigned)y0 < H_,       vy1 = (unsigned)(y0 + 1) < H_;
            if (vy0) {
                const long long r0 = (long long)y0 * W_;
                if (vx0) s = fmaf(__half2float(vimg[(r0 + x0) << 5]),     wx0 * wy0, s);
                if (vx1) s = fmaf(__half2float(vimg[(r0 + x0 + 1) << 5]), wx1 * wy0, s);
            }
            if (vy1) {
                const long long r1 = (long long)(y0 + 1) * W_;
                if (vx0) s = fmaf(__half2float(vimg[(r1 + x0) << 5]),     wx0 * wy1, s);
                if (vx1) s = fmaf(__half2float(vimg[(r1 + x0 + 1) << 5]), wx1 * wy1, s);
            }
            outv = fmaf(s, lg[l * 4 + pt] * inv, outv);
        }
    }
    const int y = p / 96, x = p - y * 96;
    const size_t ob = ((size_t)t * PPIX_ + (size_t)(y + 1) * PW_ + x + 1) * 256 + (head << 5) + lane;
    __half h = __float2half(outv);
    g_xsh[ob] = h;
    g_xsl[ob] = __float2half(outv - __half2float(h));
}

// ================= launch =================
extern "C" void kernel_launch(void* const* d_in, const int* in_sizes, int n_in,
                              void* d_out, int out_size)
{
    (void)in_sizes; (void)n_in; (void)out_size;
    const float* query         = (const float*)d_in[0];
    const float* input_flatten = (const float*)d_in[1];
    const float* ref_pts       = (const float*)d_in[2];
    const float* ff     = (const float*)d_in[6];
    const float* fb     = (const float*)d_in[7];
    const float* w_off  = (const float*)d_in[8];
    const float* b_off  = (const float*)d_in[9];
    const float* w_attn = (const float*)d_in[10];
    const float* b_attn = (const float*)d_in[11];
    const float* w_val  = (const float*)d_in[12];
    const float* b_val  = (const float*)d_in[13];
    const float* w_out  = (const float*)d_in[14];
    const float* b_out  = (const float*)d_in[15];
    float* out = (float*)d_out;

    cudaFuncSetAttribute(conv_main_kernel, cudaFuncAttributeMaxDynamicSharedMemorySize, SMTOT_M);
    cudaFuncSetAttribute(conv_out_kernel,  cudaFuncAttributeMaxDynamicSharedMemorySize, SMTOT_O);

    // 0: merged input prep
    prep_x_all_kernel<<<dim3(65, 5, 2), 128>>>(input_flatten, query);
    // 1: merged weight prep
    prep_w_all_kernel<<<(9 * 1024 * 256 + 255) / 256, 256>>>(w_val, w_off, w_attn, w_out);
    // 2: flow composition
    flow_all_kernel<<<1, 1024>>>(ff, fb);
    // 3: merged value + off/attn convs (all 1-term, A double-buffered)
    conv_main_kernel<<<dim3(6, 48, 5), 256, SMTOT_M>>>(b_val, b_off, b_attn);
    // 4: deformable attention sampling
    sample_kernel<<<(T_ * HW_ * HEADS_) / 8, 256>>>(ref_pts);
    // 5: output projection (2-term)
    conv_out_kernel<<<dim3(2, 48, 5), 256, SMTOT_O>>>(b_out, out);
}

// round 14
// speedup vs baseline: 1.3887x; 1.1053x over previous
#include <cuda_runtime.h>
#include <cuda_fp16.h>
#include <cstdint>
#include <math.h>

#define T_ 5
#define H_ 64
#define W_ 96
#define HW_ (H_ * W_)
#define HEADS_ 8
#define LVLS_ 5
#define PTS_ 4
#define PW_ (W_ + 2)            // 98
#define PH_ (H_ + 2)            // 66
#define PPIX_ (PW_ * PH_)       // 6468

// ================= helpers =================
__device__ __forceinline__ uint32_t smem_u32(const void* p) {
    uint32_t a;
    asm("{ .reg .u64 t; cvta.to.shared.u64 t, %1; cvt.u32.u64 %0, t; }" : "=r"(a) : "l"(p));
    return a;
}
__device__ __forceinline__ void ldsm4(uint32_t* r, uint32_t addr) {
    asm volatile("ldmatrix.sync.aligned.m8n8.x4.shared.b16 {%0,%1,%2,%3}, [%4];"
        : "=r"(r[0]), "=r"(r[1]), "=r"(r[2]), "=r"(r[3]) : "r"(addr));
}
__device__ __forceinline__ void mma16816(float* c, const uint32_t* a, uint32_t b0, uint32_t b1) {
    asm volatile(
        "mma.sync.aligned.m16n8k16.row.col.f32.f16.f16.f32 "
        "{%0,%1,%2,%3}, {%4,%5,%6,%7}, {%8,%9}, {%0,%1,%2,%3};"
        : "+f"(c[0]), "+f"(c[1]), "+f"(c[2]), "+f"(c[3])
        : "r"(a[0]), "r"(a[1]), "r"(a[2]), "r"(a[3]), "r"(b0), "r"(b1));
}
__device__ __forceinline__ void cp16(uint32_t dst, const void* src, int ok) {
    asm volatile(
        "{\n\t.reg .pred p;\n\tsetp.ne.s32 p, %2, 0;\n\t"
        "@p cp.async.cg.shared.global [%0], [%1], 16;\n\t"
        "@!p cp.async.cg.shared.global [%0], [%1], 16, 0;\n\t}"
        :: "r"(dst), "l"(src), "r"(ok) : "memory");
}
__device__ __forceinline__ void cp_async_wait_all() {
    asm volatile("cp.async.commit_group;\ncp.async.wait_group 0;" ::: "memory");
}

// ================= scratch =================
__device__ __align__(16) __half g_xfh[(size_t)T_ * PPIX_ * 256];
__device__ __align__(16) __half g_xqh[(size_t)T_ * PPIX_ * 256];
__device__ __align__(16) __half g_xsh[(size_t)T_ * PPIX_ * 256];
__device__ __align__(16) __half g_wv[9 * 256 * 256];
__device__ __align__(16) __half g_wp[9 * 512 * 256];   // off+attn fused (co 480..511 = zero pad)
__device__ __align__(16) __half g_wu[9 * 256 * 256];
__device__ __align__(16) __half g_value[(size_t)T_ * HEADS_ * HW_ * 32];   // [t][head][pix][dh]
__device__ float g_off  [(size_t)T_ * 320 * HW_];
__device__ float g_attn [(size_t)T_ * 160 * HW_];
__device__ float g_adds [(size_t)4 * 5 * 2 * HW_];

// ================= merged input prep (vectorized stores) =================
// grid (65, 5, 2). z=0: input_flatten -> g_xfh [+ borders of xf and xs]
//                  z=1: query -> g_xqh
__global__ void __launch_bounds__(128) prep_x_all_kernel(
    const float* __restrict__ src0, const float* __restrict__ src1)
{
    const int t = blockIdx.y, z = blockIdx.z, tid = threadIdx.x;
    __half* dh = z ? g_xqh : g_xfh;

    if (blockIdx.x == 64) {   // border zeroing
        for (int pp = tid; pp < PPIX_; pp += 128) {
            int py = pp / PW_, px = pp - py * PW_;
            if (py == 0 || py == PH_ - 1 || px == 0 || px == PW_ - 1) {
                size_t o = ((size_t)t * PPIX_ + pp) * 256;
                uint4 z4 = make_uint4(0, 0, 0, 0);
#pragma unroll
                for (int c = 0; c < 32; c++) {
                    *(uint4*)((char*)dh + (o + c * 8) * 2) = z4;
                    if (z == 0) *(uint4*)((char*)g_xsh + (o + c * 8) * 2) = z4;
                }
            }
        }
        return;
    }

    const float* src = z ? src1 : src0;
    const int y = blockIdx.x;
    __shared__ float s[64][97];
    for (int cib = 0; cib < 4; cib++) {
        __syncthreads();
        for (int i = tid; i < 64 * 96; i += 128) {
            int r = i / 96, c = i - r * 96;
            s[r][c] = src[((size_t)(t * 256 + cib * 64 + r)) * HW_ + y * 96 + c];
        }
        __syncthreads();
        // 8 threads per pixel, each packs 8 ci into one uint4 (16B) store
        const int cq = tid & 7;
        for (int base = 0; base < 96; base += 16) {
            const int xp = base + (tid >> 3);
            uint32_t pk[4];
#pragma unroll
            for (int j = 0; j < 4; j++) {
                __half2 h2 = __floats2half2_rn(s[cq * 8 + j * 2][xp], s[cq * 8 + j * 2 + 1][xp]);
                pk[j] = *(uint32_t*)&h2;
            }
            size_t ob = ((size_t)t * PPIX_ + (size_t)(y + 1) * PW_ + xp + 1) * 256 + cib * 64 + cq * 8;
            *(uint4*)((char*)dh + ob * 2) = make_uint4(pk[0], pk[1], pk[2], pk[3]);
        }
    }
}

// ================= merged weight prep (smem-staged, coalesced) =================
// grid 1024 = one block per output co row; block 256.
// [0,256)=wv | [256,576)=wp/off | [576,736)=wp/attn | [736,768)=wp zero-pad | [768,1024)=wu
__global__ void __launch_bounds__(256) prep_w_all_kernel(
    const float* __restrict__ w_val, const float* __restrict__ w_off,
    const float* __restrict__ w_attn, const float* __restrict__ w_out)
{
    const int co_all = blockIdx.x, tid = threadIdx.x;
    const float* wrow; __half* dst; int co, CoPad;
    if (co_all < 256)      { dst = g_wv; co = co_all;       CoPad = 256; wrow = w_val  + (size_t)co * 2304; }
    else if (co_all < 576) { dst = g_wp; co = co_all - 256; CoPad = 512; wrow = w_off  + (size_t)co * 2304; }
    else if (co_all < 736) { dst = g_wp; co = co_all - 256; CoPad = 512; wrow = w_attn + (size_t)(co - 320) * 2304; }
    else if (co_all < 768) {
        // zero-fill pad rows 480..511 of g_wp
        int co_p = co_all - 256;
#pragma unroll
        for (int shift = 0; shift < 9; shift++)
            g_wp[((size_t)(shift * 512 + co_p)) * 256 + tid] = __float2half(0.f);
        return;
    }
    else                   { dst = g_wu; co = co_all - 768; CoPad = 256; wrow = w_out + (size_t)co * 2304; }

    __shared__ float s[2304];
    for (int i = tid; i < 2304; i += 256) s[i] = wrow[i];
    __syncthreads();
#pragma unroll
    for (int shift = 0; shift < 9; shift++)
        dst[((size_t)(shift * CoPad + co)) * 256 + tid] = __float2half(s[tid * 9 + shift]);
}

// ================= 1-term HMMA implicit-GEMM 3x3 conv =================
#define BROWS  330
#define BBYTES (BROWS * 128)            // 42240
#define M_A_OFF  BBYTES                 // 42240
#define SMTOT_M  (BBYTES + 32768)       // 75008

__device__ __forceinline__ void conv_body1(char* smem,
    const __half* __restrict__ wgt, const __half* __restrict__ xh,
    const float* __restrict__ bias1, const float* __restrict__ bias2,
    float* __restrict__ out, int CoPad, int layout, int co0)
{
    const uint32_t sb = smem_u32(smem);
    const int tid = threadIdx.x, wid = tid >> 5, lane = tid & 31;
    const int warp_m = wid & 3, warp_n = wid >> 2;
    const int t = blockIdx.z, o0 = blockIdx.y << 7;
    const int pmin = o0 + 2 * (o0 / 96);

    float C[2][8][4];
#pragma unroll
    for (int m = 0; m < 2; m++)
#pragma unroll
        for (int n = 0; n < 8; n++)
#pragma unroll
            for (int k = 0; k < 4; k++) C[m][n][k] = 0.f;

    const int kh_b = (lane >> 3) & 1;
    const int kh_a = lane >> 4;
    int prow[4];
#pragma unroll
    for (int j = 0; j < 4; j++) {
        int nl = warp_n * 64 + j * 16 + ((lane >> 4) << 3) + (lane & 7);
        int o = o0 + nl;
        prow[j] = o + 2 * (o / 96) + 99 - pmin;
    }
    int arow[2];
#pragma unroll
    for (int m = 0; m < 2; m++) arow[m] = warp_m * 32 + m * 16 + (lane & 15);

    const int ac = tid & 7;
    uint32_t adof[4];
#pragma unroll
    for (int i = 0; i < 4; i++) {
        int ar = (tid >> 3) + i * 32;
        adof[i] = ar * 128 + ((ac ^ (ar & 7)) << 4);
    }

    auto fetch_A = [&](int cs, uint4* regs) {
        const int chunk = cs / 9, shift = cs - chunk * 9;
#pragma unroll
        for (int i = 0; i < 4; i++) {
            int row = (tid >> 3) + i * 32;
            regs[i] = *(const uint4*)((const char*)wgt +
                (((size_t)(shift * CoPad + co0 + row)) * 256 + chunk * 64) * 2 + ac * 16);
        }
    };
    auto store_A = [&](int buf, const uint4* regs) {
        char* st = smem + M_A_OFF + buf * 16384;
#pragma unroll
        for (int i = 0; i < 4; i++)
            *(uint4*)(st + adof[i]) = regs[i];
    };
    auto load_B = [&](int chunk) {
        const int prem = PPIX_ - pmin;
        const char* bh = (const char*)xh + (((size_t)t * PPIX_ + pmin) * 256 + chunk * 64) * 2;
#pragma unroll
        for (int i = 0; i < 11; i++) {
            int idx = tid + i * 256;
            if (idx < BROWS * 8) {
                int r = idx >> 3, c = idx & 7;
                uint32_t dof = r * 128 + ((c ^ (r & 7)) << 4);
                int ok = (r < prem);
                int rs = ok ? r : 0;
                cp16(sb + dof, bh + (size_t)rs * 512 + c * 16, ok);
            }
        }
    };

    load_B(0);
    {
        uint4 a0[4];
        fetch_A(0, a0);
        store_A(0, a0);
    }
    cp_async_wait_all();
    __syncthreads();

    for (int cs = 0; cs < 36; cs++) {
        const int shift = cs % 9;
        uint4 apre[4];
        if (cs + 1 < 36) fetch_A(cs + 1, apre);

        const uint32_t AS = sb + M_A_OFF + (cs & 1) * 16384;
        const int off = (shift / 3 - 1) * PW_ + (shift % 3 - 1);
#pragma unroll
        for (int ks = 0; ks < 4; ks++) {
            uint32_t a[2][4], b[4][4];
#pragma unroll
            for (int m = 0; m < 2; m++) {
                int c = ks * 2 + kh_a;
                ldsm4(a[m], AS + arow[m] * 128 + ((c ^ (arow[m] & 7)) << 4));
            }
#pragma unroll
            for (int j = 0; j < 4; j++) {
                int r = prow[j] + off;
                int c = ks * 2 + kh_b;
                ldsm4(b[j], sb + r * 128 + ((c ^ (r & 7)) << 4));
            }
#pragma unroll
            for (int m = 0; m < 2; m++)
#pragma unroll
                for (int n = 0; n < 8; n++)
                    mma16816(C[m][n], a[m], b[n >> 1][(n & 1) * 2], b[n >> 1][(n & 1) * 2 + 1]);
        }

        if (cs + 1 < 36) store_A((cs + 1) & 1, apre);
        if (shift == 8 && cs + 1 < 36) {
            __syncthreads();
            load_B(cs / 9 + 1);
            cp_async_wait_all();
        }
        __syncthreads();
    }

    // epilogue
#pragma unroll
    for (int m = 0; m < 2; m++) {
        const int coA = co0 + warp_m * 32 + m * 16 + (lane >> 2);
#pragma unroll
        for (int n = 0; n < 8; n++) {
            const int px = o0 + warp_n * 64 + n * 8 + ((lane & 3) << 1);
#pragma unroll
            for (int half = 0; half < 2; half++) {
                const int co = coA + half * 8;
                const float v0 = C[m][n][half * 2 + 0];
                const float v1 = C[m][n][half * 2 + 1];
                if (layout == 0) {
                    const float bv = bias1[co];
                    float* op = out + ((size_t)t * 256 + co) * HW_ + px;
                    op[0] = v0 + bv; op[1] = v1 + bv;
                } else if (layout == 1) {
                    const float bv = bias1[co];
                    const int head = co >> 5, dh = co & 31;
                    __half* op = g_value + (((size_t)(t * 8 + head) * HW_ + px) << 5) + dh;
                    op[0]  = __float2half(v0 + bv);
                    op[32] = __float2half(v1 + bv);
                } else {
                    if (co < 480) {
                        float bv; float* op;
                        if (co < 320) { bv = bias1[co];       op = g_off  + ((size_t)t * 320 + co)       * HW_ + px; }
                        else          { bv = bias2[co - 320]; op = g_attn + ((size_t)t * 160 + co - 320) * HW_ + px; }
                        op[0] = v0 + bv; op[1] = v1 + bv;
                    }
                }
            }
        }
    }
}

__global__ void __launch_bounds__(256, 2) conv_main_kernel(
    const float* __restrict__ b_val, const float* __restrict__ b_off, const float* __restrict__ b_attn)
{
    extern __shared__ char smem[];
    if (blockIdx.x < 2)
        conv_body1(smem, g_wv, g_xfh, b_val, nullptr, nullptr, 256, 1, (int)blockIdx.x << 7);
    else
        conv_body1(smem, g_wp, g_xqh, b_off, b_attn, nullptr, 512, 2, ((int)blockIdx.x - 2) << 7);
}

__global__ void __launch_bounds__(256, 2) conv_out_kernel(
    const float* __restrict__ b_out, float* __restrict__ out)
{
    extern __shared__ char smem[];
    conv_body1(smem, g_wu, g_xsh, b_out, nullptr, out, 256, 0, (int)blockIdx.x << 7);
}

// ================= fused flow composition (single block) =================
__constant__ int c_flow_steps[9][3] = {
    {1,  7,  2},  {2, 13,  3},  {3, 19,  4},
    {7, 13,  8},  {8, 19,  9},  {13, 19, 14},
    {11, 5, 10},  {17, 11, 16}, {16, 5, 15},
};

__global__ void __launch_bounds__(1024) flow_all_kernel(
    const float* __restrict__ ff, const float* __restrict__ fb)
{
    const int tid = threadIdx.x;
    for (int p = tid; p < HW_; p += 1024) {
#pragma unroll
        for (int i = 0; i < 4; i++)
#pragma unroll
            for (int j = 0; j < 5; j++) {
                g_adds[((i * 5 + j) * 2 + 0) * HW_ + p] = 0.f;
                g_adds[((i * 5 + j) * 2 + 1) * HW_ + p] = 0.f;
            }
#pragma unroll
        for (int k = 0; k < 4; k++) {
            g_adds[((k * 5 + (k + 1)) * 2 + 0) * HW_ + p] = ff[(k * 2 + 0) * HW_ + p];
            g_adds[((k * 5 + (k + 1)) * 2 + 1) * HW_ + p] = ff[(k * 2 + 1) * HW_ + p];
        }
#pragma unroll
        for (int k = 0; k < 3; k++) {
            g_adds[(((k + 1) * 5 + k) * 2 + 0) * HW_ + p] = fb[(k * 2 + 0) * HW_ + p];
            g_adds[(((k + 1) * 5 + k) * 2 + 1) * HW_ + p] = fb[(k * 2 + 1) * HW_ + p];
        }
    }
    __syncthreads();
    for (int step = 0; step < 9; step++) {
        const float* bptr = g_adds + c_flow_steps[step][0] * 2 * HW_;
        const float* tgt  = g_adds + c_flow_steps[step][1] * 2 * HW_;
        float*       dst  = g_adds + c_flow_steps[step][2] * 2 * HW_;
        for (int p = tid; p < HW_; p += 1024) {
            int y = p / W_, x = p - y * W_;
            float fx = bptr[p], fy = bptr[HW_ + p];
            float px = (float)x + fx, py = (float)y + fy;
            float x0f = floorf(px), y0f = floorf(py);
            int   x0 = (int)x0f, y0 = (int)y0f;
            float wx1 = px - x0f, wx0 = 1.f - wx1;
            float wy1 = py - y0f, wy0 = 1.f - wy1;
            float s0 = 0.f, s1 = 0.f;
            const int xs[4] = {x0, x0 + 1, x0, x0 + 1};
            const int ys[4] = {y0, y0, y0 + 1, y0 + 1};
            const float ws[4] = {wx0 * wy0, wx1 * wy0, wx0 * wy1, wx1 * wy1};
#pragma unroll
            for (int k = 0; k < 4; k++) {
                if ((unsigned)xs[k] < W_ && (unsigned)ys[k] < H_) {
                    int idx = ys[k] * W_ + xs[k];
                    s0 = fmaf(tgt[idx], ws[k], s0);
                    s1 = fmaf(tgt[HW_ + idx], ws[k], s1);
                }
            }
            dst[p]       = fx + s0;
            dst[HW_ + p] = fy + s1;
        }
        __syncthreads();
    }
}

// ================= deformable sampling (fp16 value cache, hi-only output) =================
__global__ void __launch_bounds__(256) sample_kernel(const float* __restrict__ ref_pts)
{
    const int item = blockIdx.x * 8 + (threadIdx.x >> 5);
    const int lane = threadIdx.x & 31;
    const int head = item & 7;
    const int q    = item >> 3;
    const int t    = q / HW_;
    const int p    = q - t * HW_;
    const int ri   = (t == 4) ? 3 : t;

    const float* attn_base = g_attn + (size_t)t * 160 * HW_ + (size_t)head * 20 * HW_ + p;
    float lg[20];
    float mx = -1e30f;
#pragma unroll
    for (int i = 0; i < 20; i++) { lg[i] = attn_base[(size_t)i * HW_]; mx = fmaxf(mx, lg[i]); }
    float ssum = 0.f;
#pragma unroll
    for (int i = 0; i < 20; i++) { lg[i] = __expf(lg[i] - mx); ssum += lg[i]; }
    const float inv = 1.f / ssum;

    const float* off_base = g_off + (size_t)t * 320 * HW_ + p;
    float outv = 0.f;
#pragma unroll
    for (int l = 0; l < LVLS_; l++) {
        const float ax = g_adds[((ri * 5 + l) * 2 + 0) * HW_ + p];
        const float ay = g_adds[((ri * 5 + l) * 2 + 1) * HW_ + p];
        const float rx = ref_pts[((size_t)q * 5 + l) * 2 + 0];
        const float ry = ref_pts[((size_t)q * 5 + l) * 2 + 1];
        const __half* vimg = g_value + ((size_t)(l * 8 + head) * HW_ << 5) + lane;
#pragma unroll
        for (int pt = 0; pt < PTS_; pt++) {
            const int ch = ((head * 5 + l) * 4 + pt) * 2;
            const float ox = off_base[(size_t)ch * HW_] + ax;
            const float oy = off_base[(size_t)(ch + 1) * HW_] + ay;
            const float px = fmaf(rx, (float)W_, ox) - 0.5f;
            const float py = fmaf(ry, (float)H_, oy) - 0.5f;
            const float x0f = floorf(px), y0f = floorf(py);
            const int   x0 = (int)x0f, y0 = (int)y0f;
            const float wx1 = px - x0f, wx0 = 1.f - wx1;
            const float wy1 = py - y0f, wy0 = 1.f - wy1;
            float s = 0.f;
            const bool vx0 = (unsigned)x0 < W_,       vx1 = (unsigned)(x0 + 1) < W_;
            const bool vy0 = (unsigned)y0 < H_,       vy1 = (unsigned)(y0 + 1) < H_;
            if (vy0) {
                const long long r0 = (long long)y0 * W_;
                if (vx0) s = fmaf(__half2float(vimg[(r0 + x0) << 5]),     wx0 * wy0, s);
                if (vx1) s = fmaf(__half2float(vimg[(r0 + x0 + 1) << 5]), wx1 * wy0, s);
            }
            if (vy1) {
                const long long r1 = (long long)(y0 + 1) * W_;
                if (vx0) s = fmaf(__half2float(vimg[(r1 + x0) << 5]),     wx0 * wy1, s);
                if (vx1) s = fmaf(__half2float(vimg[(r1 + x0 + 1) << 5]), wx1 * wy1, s);
            }
            outv = fmaf(s, lg[l * 4 + pt] * inv, outv);
        }
    }
    const int y = p / 96, x = p - y * 96;
    const size_t ob = ((size_t)t * PPIX_ + (size_t)(y + 1) * PW_ + x + 1) * 256 + (head << 5) + lane;
    g_xsh[ob] = __float2half(outv);
}

// ================= launch =================
extern "C" void kernel_launch(void* const* d_in, const int* in_sizes, int n_in,
                              void* d_out, int out_size)
{
    (void)in_sizes; (void)n_in; (void)out_size;
    const float* query         = (const float*)d_in[0];
    const float* input_flatten = (const float*)d_in[1];
    const float* ref_pts       = (const float*)d_in[2];
    const float* ff     = (const float*)d_in[6];
    const float* fb     = (const float*)d_in[7];
    const float* w_off  = (const float*)d_in[8];
    const float* b_off  = (const float*)d_in[9];
    const float* w_attn = (const float*)d_in[10];
    const float* b_attn = (const float*)d_in[11];
    const float* w_val  = (const float*)d_in[12];
    const float* b_val  = (const float*)d_in[13];
    const float* w_out  = (const float*)d_in[14];
    const float* b_out  = (const float*)d_in[15];
    float* out = (float*)d_out;

    cudaFuncSetAttribute(conv_main_kernel, cudaFuncAttributeMaxDynamicSharedMemorySize, SMTOT_M);
    cudaFuncSetAttribute(conv_out_kernel,  cudaFuncAttributeMaxDynamicSharedMemorySize, SMTOT_M);

    // 0: merged input prep (vectorized)
    prep_x_all_kernel<<<dim3(65, 5, 2), 128>>>(input_flatten, query);
    // 1: merged weight prep (smem-staged)
    prep_w_all_kernel<<<1024, 256>>>(w_val, w_off, w_attn, w_out);
    // 2: flow composition
    flow_all_kernel<<<1, 1024>>>(ff, fb);
    // 3: merged value + off/attn convs (1-term)
    conv_main_kernel<<<dim3(6, 48, 5), 256, SMTOT_M>>>(b_val, b_off, b_attn);
    // 4: deformable attention sampling
    sample_kernel<<<(T_ * HW_ * HEADS_) / 8, 256>>>(ref_pts);
    // 5: output projection (1-term)
    conv_out_kernel<<<dim3(2, 48, 5), 256, SMTOT_M>>>(b_out, out);
}

// round 15
// speedup vs baseline: 1.6401x; 1.1810x over previous
#include <cuda_runtime.h>
#include <cuda_fp16.h>
#include <cstdint>
#include <math.h>

#define T_ 5
#define H_ 64
#define W_ 96
#define HW_ (H_ * W_)
#define HEADS_ 8
#define LVLS_ 5
#define PTS_ 4
#define PW_ (W_ + 2)            // 98
#define PH_ (H_ + 2)            // 66
#define PPIX_ (PW_ * PH_)       // 6468

// ================= helpers =================
__device__ __forceinline__ uint32_t smem_u32(const void* p) {
    uint32_t a;
    asm("{ .reg .u64 t; cvta.to.shared.u64 t, %1; cvt.u32.u64 %0, t; }" : "=r"(a) : "l"(p));
    return a;
}
__device__ __forceinline__ void ldsm4(uint32_t* r, uint32_t addr) {
    asm volatile("ldmatrix.sync.aligned.m8n8.x4.shared.b16 {%0,%1,%2,%3}, [%4];"
        : "=r"(r[0]), "=r"(r[1]), "=r"(r[2]), "=r"(r[3]) : "r"(addr));
}
__device__ __forceinline__ void mma16816(float* c, const uint32_t* a, uint32_t b0, uint32_t b1) {
    asm volatile(
        "mma.sync.aligned.m16n8k16.row.col.f32.f16.f16.f32 "
        "{%0,%1,%2,%3}, {%4,%5,%6,%7}, {%8,%9}, {%0,%1,%2,%3};"
        : "+f"(c[0]), "+f"(c[1]), "+f"(c[2]), "+f"(c[3])
        : "r"(a[0]), "r"(a[1]), "r"(a[2]), "r"(a[3]), "r"(b0), "r"(b1));
}
__device__ __forceinline__ void cp16(uint32_t dst, const void* src, int ok) {
    asm volatile(
        "{\n\t.reg .pred p;\n\tsetp.ne.s32 p, %2, 0;\n\t"
        "@p cp.async.cg.shared.global [%0], [%1], 16;\n\t"
        "@!p cp.async.cg.shared.global [%0], [%1], 16, 0;\n\t}"
        :: "r"(dst), "l"(src), "r"(ok) : "memory");
}
__device__ __forceinline__ void cp_async_wait_all() {
    asm volatile("cp.async.commit_group;\ncp.async.wait_group 0;" ::: "memory");
}

// ================= scratch =================
__device__ __align__(16) __half g_xfh[(size_t)T_ * PPIX_ * 256];
__device__ __align__(16) __half g_xqh[(size_t)T_ * PPIX_ * 256];
__device__ __align__(16) __half g_xsh[(size_t)T_ * PPIX_ * 256];
__device__ __align__(16) __half g_wv[9 * 256 * 256];
__device__ __align__(16) __half g_wp[9 * 512 * 256];   // off+attn fused (co 480..511 = zero pad)
__device__ __align__(16) __half g_wu[9 * 256 * 256];
__device__ __align__(16) __half g_value[(size_t)T_ * HEADS_ * HW_ * 32];   // [t][head][pix][dh]
__device__ __align__(16) float g_off2 [(size_t)T_ * HW_ * HEADS_ * 40];   // [t][pix][head][40]
__device__ __align__(16) float g_attn2[(size_t)T_ * HW_ * HEADS_ * 20];   // [t][pix][head][20]
__device__ float g_adds [(size_t)4 * 5 * 2 * HW_];

// ================= merged input prep (vectorized stores) =================
__global__ void __launch_bounds__(128) prep_x_all_kernel(
    const float* __restrict__ src0, const float* __restrict__ src1)
{
    const int t = blockIdx.y, z = blockIdx.z, tid = threadIdx.x;
    __half* dh = z ? g_xqh : g_xfh;

    if (blockIdx.x == 64) {   // border zeroing
        for (int pp = tid; pp < PPIX_; pp += 128) {
            int py = pp / PW_, px = pp - py * PW_;
            if (py == 0 || py == PH_ - 1 || px == 0 || px == PW_ - 1) {
                size_t o = ((size_t)t * PPIX_ + pp) * 256;
                uint4 z4 = make_uint4(0, 0, 0, 0);
#pragma unroll
                for (int c = 0; c < 32; c++) {
                    *(uint4*)((char*)dh + (o + c * 8) * 2) = z4;
                    if (z == 0) *(uint4*)((char*)g_xsh + (o + c * 8) * 2) = z4;
                }
            }
        }
        return;
    }

    const float* src = z ? src1 : src0;
    const int y = blockIdx.x;
    __shared__ float s[64][97];
    for (int cib = 0; cib < 4; cib++) {
        __syncthreads();
        for (int i = tid; i < 64 * 96; i += 128) {
            int r = i / 96, c = i - r * 96;
            s[r][c] = src[((size_t)(t * 256 + cib * 64 + r)) * HW_ + y * 96 + c];
        }
        __syncthreads();
        const int cq = tid & 7;
        for (int base = 0; base < 96; base += 16) {
            const int xp = base + (tid >> 3);
            uint32_t pk[4];
#pragma unroll
            for (int j = 0; j < 4; j++) {
                __half2 h2 = __floats2half2_rn(s[cq * 8 + j * 2][xp], s[cq * 8 + j * 2 + 1][xp]);
                pk[j] = *(uint32_t*)&h2;
            }
            size_t ob = ((size_t)t * PPIX_ + (size_t)(y + 1) * PW_ + xp + 1) * 256 + cib * 64 + cq * 8;
            *(uint4*)((char*)dh + ob * 2) = make_uint4(pk[0], pk[1], pk[2], pk[3]);
        }
    }
}

// ================= merged weight prep (smem-staged, coalesced) =================
__global__ void __launch_bounds__(256) prep_w_all_kernel(
    const float* __restrict__ w_val, const float* __restrict__ w_off,
    const float* __restrict__ w_attn, const float* __restrict__ w_out)
{
    const int co_all = blockIdx.x, tid = threadIdx.x;
    const float* wrow; __half* dst; int co, CoPad;
    if (co_all < 256)      { dst = g_wv; co = co_all;       CoPad = 256; wrow = w_val  + (size_t)co * 2304; }
    else if (co_all < 576) { dst = g_wp; co = co_all - 256; CoPad = 512; wrow = w_off  + (size_t)co * 2304; }
    else if (co_all < 736) { dst = g_wp; co = co_all - 256; CoPad = 512; wrow = w_attn + (size_t)(co - 320) * 2304; }
    else if (co_all < 768) {
        int co_p = co_all - 256;
#pragma unroll
        for (int shift = 0; shift < 9; shift++)
            g_wp[((size_t)(shift * 512 + co_p)) * 256 + tid] = __float2half(0.f);
        return;
    }
    else                   { dst = g_wu; co = co_all - 768; CoPad = 256; wrow = w_out + (size_t)co * 2304; }

    __shared__ float s[2304];
    for (int i = tid; i < 2304; i += 256) s[i] = wrow[i];
    __syncthreads();
#pragma unroll
    for (int shift = 0; shift < 9; shift++)
        dst[((size_t)(shift * CoPad + co)) * 256 + tid] = __float2half(s[tid * 9 + shift]);
}

// ================= 1-term HMMA implicit-GEMM 3x3 conv =================
#define BROWS  330
#define BBYTES (BROWS * 128)            // 42240
#define M_A_OFF  BBYTES                 // 42240
#define SMTOT_M  (BBYTES + 32768)       // 75008

__device__ __forceinline__ void conv_body1(char* smem,
    const __half* __restrict__ wgt, const __half* __restrict__ xh,
    const float* __restrict__ bias1, const float* __restrict__ bias2,
    float* __restrict__ out, int CoPad, int layout, int co0)
{
    const uint32_t sb = smem_u32(smem);
    const int tid = threadIdx.x, wid = tid >> 5, lane = tid & 31;
    const int warp_m = wid & 3, warp_n = wid >> 2;
    const int t = blockIdx.z, o0 = blockIdx.y << 7;
    const int pmin = o0 + 2 * (o0 / 96);

    float C[2][8][4];
#pragma unroll
    for (int m = 0; m < 2; m++)
#pragma unroll
        for (int n = 0; n < 8; n++)
#pragma unroll
            for (int k = 0; k < 4; k++) C[m][n][k] = 0.f;

    const int kh_b = (lane >> 3) & 1;
    const int kh_a = lane >> 4;
    int prow[4];
#pragma unroll
    for (int j = 0; j < 4; j++) {
        int nl = warp_n * 64 + j * 16 + ((lane >> 4) << 3) + (lane & 7);
        int o = o0 + nl;
        prow[j] = o + 2 * (o / 96) + 99 - pmin;
    }
    int arow[2];
#pragma unroll
    for (int m = 0; m < 2; m++) arow[m] = warp_m * 32 + m * 16 + (lane & 15);

    const int ac = tid & 7;
    uint32_t adof[4];
#pragma unroll
    for (int i = 0; i < 4; i++) {
        int ar = (tid >> 3) + i * 32;
        adof[i] = ar * 128 + ((ac ^ (ar & 7)) << 4);
    }

    auto fetch_A = [&](int cs, uint4* regs) {
        const int chunk = cs / 9, shift = cs - chunk * 9;
#pragma unroll
        for (int i = 0; i < 4; i++) {
            int row = (tid >> 3) + i * 32;
            regs[i] = *(const uint4*)((const char*)wgt +
                (((size_t)(shift * CoPad + co0 + row)) * 256 + chunk * 64) * 2 + ac * 16);
        }
    };
    auto store_A = [&](int buf, const uint4* regs) {
        char* st = smem + M_A_OFF + buf * 16384;
#pragma unroll
        for (int i = 0; i < 4; i++)
            *(uint4*)(st + adof[i]) = regs[i];
    };
    auto load_B = [&](int chunk) {
        const int prem = PPIX_ - pmin;
        const char* bh = (const char*)xh + (((size_t)t * PPIX_ + pmin) * 256 + chunk * 64) * 2;
#pragma unroll
        for (int i = 0; i < 11; i++) {
            int idx = tid + i * 256;
            if (idx < BROWS * 8) {
                int r = idx >> 3, c = idx & 7;
                uint32_t dof = r * 128 + ((c ^ (r & 7)) << 4);
                int ok = (r < prem);
                int rs = ok ? r : 0;
                cp16(sb + dof, bh + (size_t)rs * 512 + c * 16, ok);
            }
        }
    };

    load_B(0);
    {
        uint4 a0[4];
        fetch_A(0, a0);
        store_A(0, a0);
    }
    cp_async_wait_all();
    __syncthreads();

    for (int cs = 0; cs < 36; cs++) {
        const int shift = cs % 9;
        uint4 apre[4];
        if (cs + 1 < 36) fetch_A(cs + 1, apre);

        const uint32_t AS = sb + M_A_OFF + (cs & 1) * 16384;
        const int off = (shift / 3 - 1) * PW_ + (shift % 3 - 1);
#pragma unroll
        for (int ks = 0; ks < 4; ks++) {
            uint32_t a[2][4], b[4][4];
#pragma unroll
            for (int m = 0; m < 2; m++) {
                int c = ks * 2 + kh_a;
                ldsm4(a[m], AS + arow[m] * 128 + ((c ^ (arow[m] & 7)) << 4));
            }
#pragma unroll
            for (int j = 0; j < 4; j++) {
                int r = prow[j] + off;
                int c = ks * 2 + kh_b;
                ldsm4(b[j], sb + r * 128 + ((c ^ (r & 7)) << 4));
            }
#pragma unroll
            for (int m = 0; m < 2; m++)
#pragma unroll
                for (int n = 0; n < 8; n++)
                    mma16816(C[m][n], a[m], b[n >> 1][(n & 1) * 2], b[n >> 1][(n & 1) * 2 + 1]);
        }

        if (cs + 1 < 36) store_A((cs + 1) & 1, apre);
        if (shift == 8 && cs + 1 < 36) {
            __syncthreads();
            load_B(cs / 9 + 1);
            cp_async_wait_all();
        }
        __syncthreads();
    }

    // epilogue
#pragma unroll
    for (int m = 0; m < 2; m++) {
        const int coA = co0 + warp_m * 32 + m * 16 + (lane >> 2);
#pragma unroll
        for (int n = 0; n < 8; n++) {
            const int px = o0 + warp_n * 64 + n * 8 + ((lane & 3) << 1);
#pragma unroll
            for (int half = 0; half < 2; half++) {
                const int co = coA + half * 8;
                const float v0 = C[m][n][half * 2 + 0];
                const float v1 = C[m][n][half * 2 + 1];
                if (layout == 0) {
                    const float bv = bias1[co];
                    float* op = out + ((size_t)t * 256 + co) * HW_ + px;
                    op[0] = v0 + bv; op[1] = v1 + bv;
                } else if (layout == 1) {
                    const float bv = bias1[co];
                    const int head = co >> 5, dh = co & 31;
                    __half* op = g_value + (((size_t)(t * 8 + head) * HW_ + px) << 5) + dh;
                    op[0]  = __float2half(v0 + bv);
                    op[32] = __float2half(v1 + bv);
                } else {
                    if (co < 320) {
                        const int head = co / 40, within = co - head * 40;
                        const float bv = bias1[co];
                        float* op = g_off2 + (((size_t)t * HW_ + px) * 8 + head) * 40 + within;
                        op[0]   = v0 + bv;
                        op[320] = v1 + bv;          // next pixel: +8*40
                    } else if (co < 480) {
                        const int c2 = co - 320;
                        const int head = c2 / 20, within = c2 - head * 20;
                        const float bv = bias2[c2];
                        float* op = g_attn2 + (((size_t)t * HW_ + px) * 8 + head) * 20 + within;
                        op[0]   = v0 + bv;
                        op[160] = v1 + bv;          // next pixel: +8*20
                    }
                }
            }
        }
    }
}

__global__ void __launch_bounds__(256, 2) conv_main_kernel(
    const float* __restrict__ b_val, const float* __restrict__ b_off, const float* __restrict__ b_attn)
{
    extern __shared__ char smem[];
    if (blockIdx.x < 2)
        conv_body1(smem, g_wv, g_xfh, b_val, nullptr, nullptr, 256, 1, (int)blockIdx.x << 7);
    else
        conv_body1(smem, g_wp, g_xqh, b_off, b_attn, nullptr, 512, 2, ((int)blockIdx.x - 2) << 7);
}

__global__ void __launch_bounds__(256, 2) conv_out_kernel(
    const float* __restrict__ b_out, float* __restrict__ out)
{
    extern __shared__ char smem[];
    conv_body1(smem, g_wu, g_xsh, b_out, nullptr, out, 256, 0, (int)blockIdx.x << 7);
}

// ================= fused flow composition (single block) =================
__constant__ int c_flow_steps[9][3] = {
    {1,  7,  2},  {2, 13,  3},  {3, 19,  4},
    {7, 13,  8},  {8, 19,  9},  {13, 19, 14},
    {11, 5, 10},  {17, 11, 16}, {16, 5, 15},
};

__global__ void __launch_bounds__(1024) flow_all_kernel(
    const float* __restrict__ ff, const float* __restrict__ fb)
{
    const int tid = threadIdx.x;
    for (int p = tid; p < HW_; p += 1024) {
#pragma unroll
        for (int i = 0; i < 4; i++)
#pragma unroll
            for (int j = 0; j < 5; j++) {
                g_adds[((i * 5 + j) * 2 + 0) * HW_ + p] = 0.f;
                g_adds[((i * 5 + j) * 2 + 1) * HW_ + p] = 0.f;
            }
#pragma unroll
        for (int k = 0; k < 4; k++) {
            g_adds[((k * 5 + (k + 1)) * 2 + 0) * HW_ + p] = ff[(k * 2 + 0) * HW_ + p];
            g_adds[((k * 5 + (k + 1)) * 2 + 1) * HW_ + p] = ff[(k * 2 + 1) * HW_ + p];
        }
#pragma unroll
        for (int k = 0; k < 3; k++) {
            g_adds[(((k + 1) * 5 + k) * 2 + 0) * HW_ + p] = fb[(k * 2 + 0) * HW_ + p];
            g_adds[(((k + 1) * 5 + k) * 2 + 1) * HW_ + p] = fb[(k * 2 + 1) * HW_ + p];
        }
    }
    __syncthreads();
    for (int step = 0; step < 9; step++) {
        const float* bptr = g_adds + c_flow_steps[step][0] * 2 * HW_;
        const float* tgt  = g_adds + c_flow_steps[step][1] * 2 * HW_;
        float*       dst  = g_adds + c_flow_steps[step][2] * 2 * HW_;
        for (int p = tid; p < HW_; p += 1024) {
            int y = p / W_, x = p - y * W_;
            float fx = bptr[p], fy = bptr[HW_ + p];
            float px = (float)x + fx, py = (float)y + fy;
            float x0f = floorf(px), y0f = floorf(py);
            int   x0 = (int)x0f, y0 = (int)y0f;
            float wx1 = px - x0f, wx0 = 1.f - wx1;
            float wy1 = py - y0f, wy0 = 1.f - wy1;
            float s0 = 0.f, s1 = 0.f;
            const int xs[4] = {x0, x0 + 1, x0, x0 + 1};
            const int ys[4] = {y0, y0, y0 + 1, y0 + 1};
            const float ws[4] = {wx0 * wy0, wx1 * wy0, wx0 * wy1, wx1 * wy1};
#pragma unroll
            for (int k = 0; k < 4; k++) {
                if ((unsigned)xs[k] < W_ && (unsigned)ys[k] < H_) {
                    int idx = ys[k] * W_ + xs[k];
                    s0 = fmaf(tgt[idx], ws[k], s0);
                    s1 = fmaf(tgt[HW_ + idx], ws[k], s1);
                }
            }
            dst[p]       = fx + s0;
            dst[HW_ + p] = fy + s1;
        }
        __syncthreads();
    }
}

// ================= deformable sampling (vectorized uniforms, unconditional gathers) =================
__global__ void __launch_bounds__(256) sample_kernel(const float* __restrict__ ref_pts)
{
    const int item = blockIdx.x * 8 + (threadIdx.x >> 5);
    const int lane = threadIdx.x & 31;
    const int head = item & 7;
    const int q    = item >> 3;
    const int t    = q / HW_;
    const int p    = q - t * HW_;
    const int ri   = (t == 4) ? 3 : t;

    // softmax logits: 20 contiguous floats (5x float4)
    const float* aw = g_attn2 + (((size_t)t * HW_ + p) * 8 + head) * 20;
    float lg[20];
#pragma unroll
    for (int i = 0; i < 5; i++) {
        float4 f = *(const float4*)(aw + i * 4);
        lg[i * 4 + 0] = f.x; lg[i * 4 + 1] = f.y; lg[i * 4 + 2] = f.z; lg[i * 4 + 3] = f.w;
    }
    float mx = -1e30f;
#pragma unroll
    for (int i = 0; i < 20; i++) mx = fmaxf(mx, lg[i]);
    float ssum = 0.f;
#pragma unroll
    for (int i = 0; i < 20; i++) { lg[i] = __expf(lg[i] - mx); ssum += lg[i]; }
    const float inv = 1.f / ssum;

    const float* ofp = g_off2 + (((size_t)t * HW_ + p) * 8 + head) * 40;
    float outv = 0.f;
#pragma unroll
    for (int l = 0; l < LVLS_; l++) {
        const float ax = g_adds[((ri * 5 + l) * 2 + 0) * HW_ + p];
        const float ay = g_adds[((ri * 5 + l) * 2 + 1) * HW_ + p];
        const float rx = ref_pts[((size_t)q * 5 + l) * 2 + 0];
        const float ry = ref_pts[((size_t)q * 5 + l) * 2 + 1];
        float o8[8];
        {
            float4 q0 = *(const float4*)(ofp + l * 8);
            float4 q1 = *(const float4*)(ofp + l * 8 + 4);
            o8[0] = q0.x; o8[1] = q0.y; o8[2] = q0.z; o8[3] = q0.w;
            o8[4] = q1.x; o8[5] = q1.y; o8[6] = q1.z; o8[7] = q1.w;
        }
        const __half* vimg = g_value + ((size_t)(l * 8 + head) * HW_ << 5) + lane;
#pragma unroll
        for (int pt = 0; pt < PTS_; pt++) {
            const float ox = o8[pt * 2 + 0] + ax;
            const float oy = o8[pt * 2 + 1] + ay;
            const float px = fmaf(rx, (float)W_, ox) - 0.5f;
            const float py = fmaf(ry, (float)H_, oy) - 0.5f;
            const float x0f = floorf(px), y0f = floorf(py);
            const int   x0 = (int)x0f, y0 = (int)y0f;
            const float wx1 = px - x0f, wx0 = 1.f - wx1;
            const float wy1 = py - y0f, wy0 = 1.f - wy1;
            const bool vx0 = (unsigned)x0 < W_,       vx1 = (unsigned)(x0 + 1) < W_;
            const bool vy0 = (unsigned)y0 < H_,       vy1 = (unsigned)(y0 + 1) < H_;
            // clamped addresses, unconditional loads, masked weights
            const int xc0 = min(max(x0, 0), W_ - 1),     xc1 = min(max(x0 + 1, 0), W_ - 1);
            const int yc0 = min(max(y0, 0), H_ - 1),     yc1 = min(max(y0 + 1, 0), H_ - 1);
            const float w00 = (vx0 && vy0) ? wx0 * wy0 : 0.f;
            const float w01 = (vx1 && vy0) ? wx1 * wy0 : 0.f;
            const float w10 = (vx0 && vy1) ? wx0 * wy1 : 0.f;
            const float w11 = (vx1 && vy1) ? wx1 * wy1 : 0.f;
            const float v00 = __half2float(vimg[((size_t)(yc0 * W_ + xc0)) << 5]);
            const float v01 = __half2float(vimg[((size_t)(yc0 * W_ + xc1)) << 5]);
            const float v10 = __half2float(vimg[((size_t)(yc1 * W_ + xc0)) << 5]);
            const float v11 = __half2float(vimg[((size_t)(yc1 * W_ + xc1)) << 5]);
            const float s = v00 * w00 + v01 * w01 + v10 * w10 + v11 * w11;
            outv = fmaf(s, lg[l * 4 + pt] * inv, outv);
        }
    }
    const int y = p / 96, x = p - y * 96;
    const size_t ob = ((size_t)t * PPIX_ + (size_t)(y + 1) * PW_ + x + 1) * 256 + (head << 5) + lane;
    g_xsh[ob] = __float2half(outv);
}

// ================= launch =================
extern "C" void kernel_launch(void* const* d_in, const int* in_sizes, int n_in,
                              void* d_out, int out_size)
{
    (void)in_sizes; (void)n_in; (void)out_size;
    const float* query         = (const float*)d_in[0];
    const float* input_flatten = (const float*)d_in[1];
    const float* ref_pts       = (const float*)d_in[2];
    const float* ff     = (const float*)d_in[6];
    const float* fb     = (const float*)d_in[7];
    const float* w_off  = (const float*)d_in[8];
    const float* b_off  = (const float*)d_in[9];
    const float* w_attn = (const float*)d_in[10];
    const float* b_attn = (const float*)d_in[11];
    const float* w_val  = (const float*)d_in[12];
    const float* b_val  = (const float*)d_in[13];
    const float* w_out  = (const float*)d_in[14];
    const float* b_out  = (const float*)d_in[15];
    float* out = (float*)d_out;

    cudaFuncSetAttribute(conv_main_kernel, cudaFuncAttributeMaxDynamicSharedMemorySize, SMTOT_M);
    cudaFuncSetAttribute(conv_out_kernel,  cudaFuncAttributeMaxDynamicSharedMemorySize, SMTOT_M);

    // 0: merged input prep
    prep_x_all_kernel<<<dim3(65, 5, 2), 128>>>(input_flatten, query);
    // 1: merged weight prep
    prep_w_all_kernel<<<1024, 256>>>(w_val, w_off, w_attn, w_out);
    // 2: flow composition
    flow_all_kernel<<<1, 1024>>>(ff, fb);
    // 3: merged value + off/attn convs (1-term)
    conv_main_kernel<<<dim3(6, 48, 5), 256, SMTOT_M>>>(b_val, b_off, b_attn);
    // 4: deformable attention sampling
    sample_kernel<<<(T_ * HW_ * HEADS_) / 8, 256>>>(ref_pts);
    // 5: output projection (1-term)
    conv_out_kernel<<<dim3(2, 48, 5), 256, SMTOT_M>>>(b_out, out);
}

// round 16
// speedup vs baseline: 1.8088x; 1.1029x over previous
#include <cuda_runtime.h>
#include <cuda_fp16.h>
#include <cstdint>
#include <math.h>

#define T_ 5
#define H_ 64
#define W_ 96
#define HW_ (H_ * W_)
#define HEADS_ 8
#define LVLS_ 5
#define PTS_ 4
#define PW_ (W_ + 2)            // 98
#define PH_ (H_ + 2)            // 66
#define PPIX_ (PW_ * PH_)       // 6468

// ================= helpers =================
__device__ __forceinline__ uint32_t smem_u32(const void* p) {
    uint32_t a;
    asm("{ .reg .u64 t; cvta.to.shared.u64 t, %1; cvt.u32.u64 %0, t; }" : "=r"(a) : "l"(p));
    return a;
}
__device__ __forceinline__ void ldsm4(uint32_t* r, uint32_t addr) {
    asm volatile("ldmatrix.sync.aligned.m8n8.x4.shared.b16 {%0,%1,%2,%3}, [%4];"
        : "=r"(r[0]), "=r"(r[1]), "=r"(r[2]), "=r"(r[3]) : "r"(addr));
}
__device__ __forceinline__ void mma16816(float* c, const uint32_t* a, uint32_t b0, uint32_t b1) {
    asm volatile(
        "mma.sync.aligned.m16n8k16.row.col.f32.f16.f16.f32 "
        "{%0,%1,%2,%3}, {%4,%5,%6,%7}, {%8,%9}, {%0,%1,%2,%3};"
        : "+f"(c[0]), "+f"(c[1]), "+f"(c[2]), "+f"(c[3])
        : "r"(a[0]), "r"(a[1]), "r"(a[2]), "r"(a[3]), "r"(b0), "r"(b1));
}
__device__ __forceinline__ void cp16(uint32_t dst, const void* src, int ok) {
    asm volatile(
        "{\n\t.reg .pred p;\n\tsetp.ne.s32 p, %2, 0;\n\t"
        "@p cp.async.cg.shared.global [%0], [%1], 16;\n\t"
        "@!p cp.async.cg.shared.global [%0], [%1], 16, 0;\n\t}"
        :: "r"(dst), "l"(src), "r"(ok) : "memory");
}
__device__ __forceinline__ void cp_async_wait_all() {
    asm volatile("cp.async.commit_group;\ncp.async.wait_group 0;" ::: "memory");
}

// ================= scratch =================
__device__ __align__(16) __half g_xfh[(size_t)T_ * PPIX_ * 256];
__device__ __align__(16) __half g_xqh[(size_t)T_ * PPIX_ * 256];
__device__ __align__(16) __half g_xsh[(size_t)T_ * PPIX_ * 256];
__device__ __align__(16) __half g_wv[9 * 256 * 256];
__device__ __align__(16) __half g_wp[9 * 512 * 256];   // off+attn fused (co 480..511 = zero pad)
__device__ __align__(16) __half g_wu[9 * 256 * 256];
__device__ __align__(16) __half g_value[(size_t)T_ * HEADS_ * HW_ * 32];   // [t][head][pix][dh]
__device__ __align__(16) float g_off2 [(size_t)T_ * HW_ * HEADS_ * 40];   // [t][pix][head][40]
__device__ __align__(16) float g_attn2[(size_t)T_ * HW_ * HEADS_ * 20];   // [t][pix][head][20]
__device__ float g_adds [(size_t)4 * 5 * 2 * HW_];

// ================= merged input prep (vectorized stores) =================
__global__ void __launch_bounds__(128) prep_x_all_kernel(
    const float* __restrict__ src0, const float* __restrict__ src1)
{
    const int t = blockIdx.y, z = blockIdx.z, tid = threadIdx.x;
    __half* dh = z ? g_xqh : g_xfh;

    if (blockIdx.x == 64) {   // border zeroing
        for (int pp = tid; pp < PPIX_; pp += 128) {
            int py = pp / PW_, px = pp - py * PW_;
            if (py == 0 || py == PH_ - 1 || px == 0 || px == PW_ - 1) {
                size_t o = ((size_t)t * PPIX_ + pp) * 256;
                uint4 z4 = make_uint4(0, 0, 0, 0);
#pragma unroll
                for (int c = 0; c < 32; c++) {
                    *(uint4*)((char*)dh + (o + c * 8) * 2) = z4;
                    if (z == 0) *(uint4*)((char*)g_xsh + (o + c * 8) * 2) = z4;
                }
            }
        }
        return;
    }

    const float* src = z ? src1 : src0;
    const int y = blockIdx.x;
    __shared__ float s[64][97];
    for (int cib = 0; cib < 4; cib++) {
        __syncthreads();
        for (int i = tid; i < 64 * 96; i += 128) {
            int r = i / 96, c = i - r * 96;
            s[r][c] = src[((size_t)(t * 256 + cib * 64 + r)) * HW_ + y * 96 + c];
        }
        __syncthreads();
        const int cq = tid & 7;
        for (int base = 0; base < 96; base += 16) {
            const int xp = base + (tid >> 3);
            uint32_t pk[4];
#pragma unroll
            for (int j = 0; j < 4; j++) {
                __half2 h2 = __floats2half2_rn(s[cq * 8 + j * 2][xp], s[cq * 8 + j * 2 + 1][xp]);
                pk[j] = *(uint32_t*)&h2;
            }
            size_t ob = ((size_t)t * PPIX_ + (size_t)(y + 1) * PW_ + xp + 1) * 256 + cib * 64 + cq * 8;
            *(uint4*)((char*)dh + ob * 2) = make_uint4(pk[0], pk[1], pk[2], pk[3]);
        }
    }
}

// ================= merged weight prep (smem-staged, coalesced) =================
__global__ void __launch_bounds__(256) prep_w_all_kernel(
    const float* __restrict__ w_val, const float* __restrict__ w_off,
    const float* __restrict__ w_attn, const float* __restrict__ w_out)
{
    const int co_all = blockIdx.x, tid = threadIdx.x;
    const float* wrow; __half* dst; int co, CoPad;
    if (co_all < 256)      { dst = g_wv; co = co_all;       CoPad = 256; wrow = w_val  + (size_t)co * 2304; }
    else if (co_all < 576) { dst = g_wp; co = co_all - 256; CoPad = 512; wrow = w_off  + (size_t)co * 2304; }
    else if (co_all < 736) { dst = g_wp; co = co_all - 256; CoPad = 512; wrow = w_attn + (size_t)(co - 320) * 2304; }
    else if (co_all < 768) {
        int co_p = co_all - 256;
#pragma unroll
        for (int shift = 0; shift < 9; shift++)
            g_wp[((size_t)(shift * 512 + co_p)) * 256 + tid] = __float2half(0.f);
        return;
    }
    else                   { dst = g_wu; co = co_all - 768; CoPad = 256; wrow = w_out + (size_t)co * 2304; }

    __shared__ float s[2304];
    for (int i = tid; i < 2304; i += 256) s[i] = wrow[i];
    __syncthreads();
#pragma unroll
    for (int shift = 0; shift < 9; shift++)
        dst[((size_t)(shift * CoPad + co)) * 256 + tid] = __float2half(s[tid * 9 + shift]);
}

// ================= 1-term HMMA implicit-GEMM 3x3 conv =================
#define BROWS  330
#define BBYTES (BROWS * 128)            // 42240
#define M_A_OFF  BBYTES                 // 42240
#define SMTOT_M  (BBYTES + 32768)       // 75008

__device__ __forceinline__ void conv_body1(char* smem,
    const __half* __restrict__ wgt, const __half* __restrict__ xh,
    const float* __restrict__ bias1, const float* __restrict__ bias2,
    float* __restrict__ out, int CoPad, int layout, int co0)
{
    const uint32_t sb = smem_u32(smem);
    const int tid = threadIdx.x, wid = tid >> 5, lane = tid & 31;
    const int warp_m = wid & 3, warp_n = wid >> 2;
    const int t = blockIdx.z, o0 = blockIdx.y << 7;
    const int pmin = o0 + 2 * (o0 / 96);

    float C[2][8][4];
#pragma unroll
    for (int m = 0; m < 2; m++)
#pragma unroll
        for (int n = 0; n < 8; n++)
#pragma unroll
            for (int k = 0; k < 4; k++) C[m][n][k] = 0.f;

    const int kh_b = (lane >> 3) & 1;
    const int kh_a = lane >> 4;
    int prow[4];
#pragma unroll
    for (int j = 0; j < 4; j++) {
        int nl = warp_n * 64 + j * 16 + ((lane >> 4) << 3) + (lane & 7);
        int o = o0 + nl;
        prow[j] = o + 2 * (o / 96) + 99 - pmin;
    }
    int arow[2];
#pragma unroll
    for (int m = 0; m < 2; m++) arow[m] = warp_m * 32 + m * 16 + (lane & 15);

    const int ac = tid & 7;
    uint32_t adof[4];
#pragma unroll
    for (int i = 0; i < 4; i++) {
        int ar = (tid >> 3) + i * 32;
        adof[i] = ar * 128 + ((ac ^ (ar & 7)) << 4);
    }

    auto fetch_A = [&](int cs, uint4* regs) {
        const int chunk = cs / 9, shift = cs - chunk * 9;
#pragma unroll
        for (int i = 0; i < 4; i++) {
            int row = (tid >> 3) + i * 32;
            regs[i] = *(const uint4*)((const char*)wgt +
                (((size_t)(shift * CoPad + co0 + row)) * 256 + chunk * 64) * 2 + ac * 16);
        }
    };
    auto store_A = [&](int buf, const uint4* regs) {
        char* st = smem + M_A_OFF + buf * 16384;
#pragma unroll
        for (int i = 0; i < 4; i++)
            *(uint4*)(st + adof[i]) = regs[i];
    };
    auto load_B = [&](int chunk) {
        const int prem = PPIX_ - pmin;
        const char* bh = (const char*)xh + (((size_t)t * PPIX_ + pmin) * 256 + chunk * 64) * 2;
#pragma unroll
        for (int i = 0; i < 11; i++) {
            int idx = tid + i * 256;
            if (idx < BROWS * 8) {
                int r = idx >> 3, c = idx & 7;
                uint32_t dof = r * 128 + ((c ^ (r & 7)) << 4);
                int ok = (r < prem);
                int rs = ok ? r : 0;
                cp16(sb + dof, bh + (size_t)rs * 512 + c * 16, ok);
            }
        }
    };

    load_B(0);
    {
        uint4 a0[4];
        fetch_A(0, a0);
        store_A(0, a0);
    }
    cp_async_wait_all();
    __syncthreads();

    for (int cs = 0; cs < 36; cs++) {
        const int shift = cs % 9;
        uint4 apre[4];
        if (cs + 1 < 36) fetch_A(cs + 1, apre);

        const uint32_t AS = sb + M_A_OFF + (cs & 1) * 16384;
        const int off = (shift / 3 - 1) * PW_ + (shift % 3 - 1);
#pragma unroll
        for (int ks = 0; ks < 4; ks++) {
            uint32_t a[2][4], b[4][4];
#pragma unroll
            for (int m = 0; m < 2; m++) {
                int c = ks * 2 + kh_a;
                ldsm4(a[m], AS + arow[m] * 128 + ((c ^ (arow[m] & 7)) << 4));
            }
#pragma unroll
            for (int j = 0; j < 4; j++) {
                int r = prow[j] + off;
                int c = ks * 2 + kh_b;
                ldsm4(b[j], sb + r * 128 + ((c ^ (r & 7)) << 4));
            }
#pragma unroll
            for (int m = 0; m < 2; m++)
#pragma unroll
                for (int n = 0; n < 8; n++)
                    mma16816(C[m][n], a[m], b[n >> 1][(n & 1) * 2], b[n >> 1][(n & 1) * 2 + 1]);
        }

        if (cs + 1 < 36) store_A((cs + 1) & 1, apre);
        if (shift == 8 && cs + 1 < 36) {
            __syncthreads();
            load_B(cs / 9 + 1);
            cp_async_wait_all();
        }
        __syncthreads();
    }

    // epilogue
#pragma unroll
    for (int m = 0; m < 2; m++) {
        const int coA = co0 + warp_m * 32 + m * 16 + (lane >> 2);
#pragma unroll
        for (int n = 0; n < 8; n++) {
            const int px = o0 + warp_n * 64 + n * 8 + ((lane & 3) << 1);
#pragma unroll
            for (int half = 0; half < 2; half++) {
                const int co = coA + half * 8;
                const float v0 = C[m][n][half * 2 + 0];
                const float v1 = C[m][n][half * 2 + 1];
                if (layout == 0) {
                    const float bv = bias1[co];
                    float* op = out + ((size_t)t * 256 + co) * HW_ + px;
                    op[0] = v0 + bv; op[1] = v1 + bv;
                } else if (layout == 1) {
                    const float bv = bias1[co];
                    const int head = co >> 5, dh = co & 31;
                    __half* op = g_value + (((size_t)(t * 8 + head) * HW_ + px) << 5) + dh;
                    op[0]  = __float2half(v0 + bv);
                    op[32] = __float2half(v1 + bv);
                } else {
                    if (co < 320) {
                        const int head = co / 40, within = co - head * 40;
                        const float bv = bias1[co];
                        float* op = g_off2 + (((size_t)t * HW_ + px) * 8 + head) * 40 + within;
                        op[0]   = v0 + bv;
                        op[320] = v1 + bv;
                    } else if (co < 480) {
                        const int c2 = co - 320;
                        const int head = c2 / 20, within = c2 - head * 20;
                        const float bv = bias2[c2];
                        float* op = g_attn2 + (((size_t)t * HW_ + px) * 8 + head) * 20 + within;
                        op[0]   = v0 + bv;
                        op[160] = v1 + bv;
                    }
                }
            }
        }
    }
}

__global__ void __launch_bounds__(256, 2) conv_main_kernel(
    const float* __restrict__ b_val, const float* __restrict__ b_off, const float* __restrict__ b_attn)
{
    extern __shared__ char smem[];
    if (blockIdx.x < 2)
        conv_body1(smem, g_wv, g_xfh, b_val, nullptr, nullptr, 256, 1, (int)blockIdx.x << 7);
    else
        conv_body1(smem, g_wp, g_xqh, b_off, b_attn, nullptr, 512, 2, ((int)blockIdx.x - 2) << 7);
}

__global__ void __launch_bounds__(256, 2) conv_out_kernel(
    const float* __restrict__ b_out, float* __restrict__ out)
{
    extern __shared__ char smem[];
    conv_body1(smem, g_wu, g_xsh, b_out, nullptr, out, 256, 0, (int)blockIdx.x << 7);
}

// ================= fused flow composition (single block) =================
__constant__ int c_flow_steps[9][3] = {
    {1,  7,  2},  {2, 13,  3},  {3, 19,  4},
    {7, 13,  8},  {8, 19,  9},  {13, 19, 14},
    {11, 5, 10},  {17, 11, 16}, {16, 5, 15},
};

__global__ void __launch_bounds__(1024) flow_all_kernel(
    const float* __restrict__ ff, const float* __restrict__ fb)
{
    const int tid = threadIdx.x;
    for (int p = tid; p < HW_; p += 1024) {
#pragma unroll
        for (int i = 0; i < 4; i++)
#pragma unroll
            for (int j = 0; j < 5; j++) {
                g_adds[((i * 5 + j) * 2 + 0) * HW_ + p] = 0.f;
                g_adds[((i * 5 + j) * 2 + 1) * HW_ + p] = 0.f;
            }
#pragma unroll
        for (int k = 0; k < 4; k++) {
            g_adds[((k * 5 + (k + 1)) * 2 + 0) * HW_ + p] = ff[(k * 2 + 0) * HW_ + p];
            g_adds[((k * 5 + (k + 1)) * 2 + 1) * HW_ + p] = ff[(k * 2 + 1) * HW_ + p];
        }
#pragma unroll
        for (int k = 0; k < 3; k++) {
            g_adds[(((k + 1) * 5 + k) * 2 + 0) * HW_ + p] = fb[(k * 2 + 0) * HW_ + p];
            g_adds[(((k + 1) * 5 + k) * 2 + 1) * HW_ + p] = fb[(k * 2 + 1) * HW_ + p];
        }
    }
    __syncthreads();
    for (int step = 0; step < 9; step++) {
        const float* bptr = g_adds + c_flow_steps[step][0] * 2 * HW_;
        const float* tgt  = g_adds + c_flow_steps[step][1] * 2 * HW_;
        float*       dst  = g_adds + c_flow_steps[step][2] * 2 * HW_;
        for (int p = tid; p < HW_; p += 1024) {
            int y = p / W_, x = p - y * W_;
            float fx = bptr[p], fy = bptr[HW_ + p];
            float px = (float)x + fx, py = (float)y + fy;
            float x0f = floorf(px), y0f = floorf(py);
            int   x0 = (int)x0f, y0 = (int)y0f;
            float wx1 = px - x0f, wx0 = 1.f - wx1;
            float wy1 = py - y0f, wy0 = 1.f - wy1;
            float s0 = 0.f, s1 = 0.f;
            const int xs[4] = {x0, x0 + 1, x0, x0 + 1};
            const int ys[4] = {y0, y0, y0 + 1, y0 + 1};
            const float ws[4] = {wx0 * wy0, wx1 * wy0, wx0 * wy1, wx1 * wy1};
#pragma unroll
            for (int k = 0; k < 4; k++) {
                if ((unsigned)xs[k] < W_ && (unsigned)ys[k] < H_) {
                    int idx = ys[k] * W_ + xs[k];
                    s0 = fmaf(tgt[idx], ws[k], s0);
                    s1 = fmaf(tgt[HW_ + idx], ws[k], s1);
                }
            }
            dst[p]       = fx + s0;
            dst[HW_ + p] = fy + s1;
        }
        __syncthreads();
    }
}

// ================= deformable sampling (paired points, half2 channels) =================
// Warp per (q, head). lane = (cp = lane&15: channel pair) x (pg = lane>>4: point parity).
// Each level: 2 iterations, each covering 2 points (one per half-warp) -> 40 tap LDGs.
__global__ void __launch_bounds__(256) sample_kernel(const float* __restrict__ ref_pts)
{
    const int item = blockIdx.x * 8 + (threadIdx.x >> 5);
    const int lane = threadIdx.x & 31;
    const int cp   = lane & 15;          // channels 2cp, 2cp+1
    const int pg   = lane >> 4;          // point parity
    const int head = item & 7;
    const int q    = item >> 3;
    const int t    = q / HW_;
    const int p    = q - t * HW_;
    const int ri   = (t == 4) ? 3 : t;

    // softmax logits: 20 contiguous floats (uniform across warp)
    const float* aw = g_attn2 + (((size_t)t * HW_ + p) * 8 + head) * 20;
    float lg[20];
#pragma unroll
    for (int i = 0; i < 5; i++) {
        float4 f = *(const float4*)(aw + i * 4);
        lg[i * 4 + 0] = f.x; lg[i * 4 + 1] = f.y; lg[i * 4 + 2] = f.z; lg[i * 4 + 3] = f.w;
    }
    float mx = -1e30f;
#pragma unroll
    for (int i = 0; i < 20; i++) mx = fmaxf(mx, lg[i]);
    float ssum = 0.f;
#pragma unroll
    for (int i = 0; i < 20; i++) { lg[i] = __expf(lg[i] - mx); ssum += lg[i]; }
    const float inv = 1.f / ssum;

    const float* ofp = g_off2 + (((size_t)t * HW_ + p) * 8 + head) * 40;
    float acc0 = 0.f, acc1 = 0.f;        // this lane's channel pair, its point subset
#pragma unroll
    for (int l = 0; l < LVLS_; l++) {
        const float ax = g_adds[((ri * 5 + l) * 2 + 0) * HW_ + p];
        const float ay = g_adds[((ri * 5 + l) * 2 + 1) * HW_ + p];
        const float rx = ref_pts[((size_t)q * 5 + l) * 2 + 0];
        const float ry = ref_pts[((size_t)q * 5 + l) * 2 + 1];
        float o8[8];
        {
            float4 q0 = *(const float4*)(ofp + l * 8);
            float4 q1 = *(const float4*)(ofp + l * 8 + 4);
            o8[0] = q0.x; o8[1] = q0.y; o8[2] = q0.z; o8[3] = q0.w;
            o8[4] = q1.x; o8[5] = q1.y; o8[6] = q1.z; o8[7] = q1.w;
        }
        const __half* vimg = g_value + ((size_t)(l * 8 + head) * HW_ << 5) + 2 * cp;
#pragma unroll
        for (int k = 0; k < 2; k++) {
            const int pt = 2 * k + pg;
            const float ox = o8[pt * 2 + 0] + ax;
            const float oy = o8[pt * 2 + 1] + ay;
            const float px = fmaf(rx, (float)W_, ox) - 0.5f;
            const float py = fmaf(ry, (float)H_, oy) - 0.5f;
            const float x0f = floorf(px), y0f = floorf(py);
            const int   x0 = (int)x0f, y0 = (int)y0f;
            const float wx1 = px - x0f, wx0 = 1.f - wx1;
            const float wy1 = py - y0f, wy0 = 1.f - wy1;
            const bool vx0 = (unsigned)x0 < W_,       vx1 = (unsigned)(x0 + 1) < W_;
            const bool vy0 = (unsigned)y0 < H_,       vy1 = (unsigned)(y0 + 1) < H_;
            const int xc0 = min(max(x0, 0), W_ - 1),  xc1 = min(max(x0 + 1, 0), W_ - 1);
            const int yc0 = min(max(y0, 0), H_ - 1),  yc1 = min(max(y0 + 1, 0), H_ - 1);
            const float w00 = (vx0 && vy0) ? wx0 * wy0 : 0.f;
            const float w01 = (vx1 && vy0) ? wx1 * wy0 : 0.f;
            const float w10 = (vx0 && vy1) ? wx0 * wy1 : 0.f;
            const float w11 = (vx1 && vy1) ? wx1 * wy1 : 0.f;
            const float2 v00 = __half22float2(*(const __half2*)(vimg + (((size_t)(yc0 * W_ + xc0)) << 5)));
            const float2 v01 = __half22float2(*(const __half2*)(vimg + (((size_t)(yc0 * W_ + xc1)) << 5)));
            const float2 v10 = __half22float2(*(const __half2*)(vimg + (((size_t)(yc1 * W_ + xc0)) << 5)));
            const float2 v11 = __half22float2(*(const __half2*)(vimg + (((size_t)(yc1 * W_ + xc1)) << 5)));
            const float wl = lg[l * 4 + pt] * inv;
            acc0 = fmaf(v00.x * w00 + v01.x * w01 + v10.x * w10 + v11.x * w11, wl, acc0);
            acc1 = fmaf(v00.y * w00 + v01.y * w01 + v10.y * w10 + v11.y * w11, wl, acc1);
        }
    }
    // combine the two point-groups (lane i += lane i+16)
    const float r0 = __shfl_down_sync(0xffffffffu, acc0, 16);
    const float r1 = __shfl_down_sync(0xffffffffu, acc1, 16);
    if (pg == 0) {
        acc0 += r0; acc1 += r1;
        const int y = p / 96, x = p - y * 96;
        const size_t ob = ((size_t)t * PPIX_ + (size_t)(y + 1) * PW_ + x + 1) * 256 + (head << 5) + 2 * cp;
        *(__half2*)(g_xsh + ob) = __floats2half2_rn(acc0, acc1);
    }
}

// ================= launch =================
extern "C" void kernel_launch(void* const* d_in, const int* in_sizes, int n_in,
                              void* d_out, int out_size)
{
    (void)in_sizes; (void)n_in; (void)out_size;
    const float* query         = (const float*)d_in[0];
    const float* input_flatten = (const float*)d_in[1];
    const float* ref_pts       = (const float*)d_in[2];
    const float* ff     = (const float*)d_in[6];
    const float* fb     = (const float*)d_in[7];
    const float* w_off  = (const float*)d_in[8];
    const float* b_off  = (const float*)d_in[9];
    const float* w_attn = (const float*)d_in[10];
    const float* b_attn = (const float*)d_in[11];
    const float* w_val  = (const float*)d_in[12];
    const float* b_val  = (const float*)d_in[13];
    const float* w_out  = (const float*)d_in[14];
    const float* b_out  = (const float*)d_in[15];
    float* out = (float*)d_out;

    cudaFuncSetAttribute(conv_main_kernel, cudaFuncAttributeMaxDynamicSharedMemorySize, SMTOT_M);
    cudaFuncSetAttribute(conv_out_kernel,  cudaFuncAttributeMaxDynamicSharedMemorySize, SMTOT_M);

    // 0: merged input prep
    prep_x_all_kernel<<<dim3(65, 5, 2), 128>>>(input_flatten, query);
    // 1: merged weight prep
    prep_w_all_kernel<<<1024, 256>>>(w_val, w_off, w_attn, w_out);
    // 2: flow composition
    flow_all_kernel<<<1, 1024>>>(ff, fb);
    // 3: merged value + off/attn convs (1-term)
    conv_main_kernel<<<dim3(6, 48, 5), 256, SMTOT_M>>>(b_val, b_off, b_attn);
    // 4: deformable attention sampling (paired-point half2)
    sample_kernel<<<(T_ * HW_ * HEADS_) / 8, 256>>>(ref_pts);
    // 5: output projection (1-term)
    conv_out_kernel<<<dim3(2, 48, 5), 256, SMTOT_M>>>(b_out, out);
}

// round 17
// speedup vs baseline: 2.0525x; 1.1347x over previous
#include <cuda_runtime.h>
#include <cuda_fp16.h>
#include <cstdint>
#include <math.h>

#define T_ 5
#define H_ 64
#define W_ 96
#define HW_ (H_ * W_)
#define HEADS_ 8
#define LVLS_ 5
#define PTS_ 4
#define PW_ (W_ + 2)            // 98
#define PH_ (H_ + 2)            // 66
#define PPIX_ (PW_ * PH_)       // 6468

// ================= helpers =================
__device__ __forceinline__ uint32_t smem_u32(const void* p) {
    uint32_t a;
    asm("{ .reg .u64 t; cvta.to.shared.u64 t, %1; cvt.u32.u64 %0, t; }" : "=r"(a) : "l"(p));
    return a;
}
__device__ __forceinline__ void ldsm4(uint32_t* r, uint32_t addr) {
    asm volatile("ldmatrix.sync.aligned.m8n8.x4.shared.b16 {%0,%1,%2,%3}, [%4];"
        : "=r"(r[0]), "=r"(r[1]), "=r"(r[2]), "=r"(r[3]) : "r"(addr));
}
__device__ __forceinline__ void mma16816(float* c, const uint32_t* a, uint32_t b0, uint32_t b1) {
    asm volatile(
        "mma.sync.aligned.m16n8k16.row.col.f32.f16.f16.f32 "
        "{%0,%1,%2,%3}, {%4,%5,%6,%7}, {%8,%9}, {%0,%1,%2,%3};"
        : "+f"(c[0]), "+f"(c[1]), "+f"(c[2]), "+f"(c[3])
        : "r"(a[0]), "r"(a[1]), "r"(a[2]), "r"(a[3]), "r"(b0), "r"(b1));
}
__device__ __forceinline__ void cp16(uint32_t dst, const void* src, int ok) {
    asm volatile(
        "{\n\t.reg .pred p;\n\tsetp.ne.s32 p, %2, 0;\n\t"
        "@p cp.async.cg.shared.global [%0], [%1], 16;\n\t"
        "@!p cp.async.cg.shared.global [%0], [%1], 16, 0;\n\t}"
        :: "r"(dst), "l"(src), "r"(ok) : "memory");
}
__device__ __forceinline__ void cp_async_wait_all() {
    asm volatile("cp.async.commit_group;\ncp.async.wait_group 0;" ::: "memory");
}

// ================= scratch =================
__device__ __align__(16) __half g_xfh[(size_t)T_ * PPIX_ * 256];
__device__ __align__(16) __half g_xqh[(size_t)T_ * PPIX_ * 256];
__device__ __align__(16) __half g_xsh[(size_t)T_ * PPIX_ * 256];
__device__ __align__(16) __half g_wv[9 * 256 * 256];
__device__ __align__(16) __half g_wp[9 * 512 * 256];   // off+attn fused (co 480..511 = zero pad)
__device__ __align__(16) __half g_wu[9 * 256 * 256];
__device__ __align__(16) __half g_value[(size_t)T_ * HEADS_ * HW_ * 32];   // [t][head][pix][dh]
__device__ __align__(16) float g_off2 [(size_t)T_ * HW_ * HEADS_ * 40];   // [t][pix][head][40]
__device__ __align__(16) float g_attn2[(size_t)T_ * HW_ * HEADS_ * 20];   // [t][pix][head][20]
__device__ float g_adds [(size_t)4 * 5 * 2 * HW_];

// ================= merged input prep (vectorized stores) =================
__global__ void __launch_bounds__(128) prep_x_all_kernel(
    const float* __restrict__ src0, const float* __restrict__ src1)
{
    const int t = blockIdx.y, z = blockIdx.z, tid = threadIdx.x;
    __half* dh = z ? g_xqh : g_xfh;

    if (blockIdx.x == 64) {   // border zeroing
        for (int pp = tid; pp < PPIX_; pp += 128) {
            int py = pp / PW_, px = pp - py * PW_;
            if (py == 0 || py == PH_ - 1 || px == 0 || px == PW_ - 1) {
                size_t o = ((size_t)t * PPIX_ + pp) * 256;
                uint4 z4 = make_uint4(0, 0, 0, 0);
#pragma unroll
                for (int c = 0; c < 32; c++) {
                    *(uint4*)((char*)dh + (o + c * 8) * 2) = z4;
                    if (z == 0) *(uint4*)((char*)g_xsh + (o + c * 8) * 2) = z4;
                }
            }
        }
        return;
    }

    const float* src = z ? src1 : src0;
    const int y = blockIdx.x;
    __shared__ float s[64][97];
    for (int cib = 0; cib < 4; cib++) {
        __syncthreads();
        for (int i = tid; i < 64 * 96; i += 128) {
            int r = i / 96, c = i - r * 96;
            s[r][c] = src[((size_t)(t * 256 + cib * 64 + r)) * HW_ + y * 96 + c];
        }
        __syncthreads();
        const int cq = tid & 7;
        for (int base = 0; base < 96; base += 16) {
            const int xp = base + (tid >> 3);
            uint32_t pk[4];
#pragma unroll
            for (int j = 0; j < 4; j++) {
                __half2 h2 = __floats2half2_rn(s[cq * 8 + j * 2][xp], s[cq * 8 + j * 2 + 1][xp]);
                pk[j] = *(uint32_t*)&h2;
            }
            size_t ob = ((size_t)t * PPIX_ + (size_t)(y + 1) * PW_ + xp + 1) * 256 + cib * 64 + cq * 8;
            *(uint4*)((char*)dh + ob * 2) = make_uint4(pk[0], pk[1], pk[2], pk[3]);
        }
    }
}

// ================= merged weight prep (smem-staged, coalesced) =================
__global__ void __launch_bounds__(256) prep_w_all_kernel(
    const float* __restrict__ w_val, const float* __restrict__ w_off,
    const float* __restrict__ w_attn, const float* __restrict__ w_out)
{
    const int co_all = blockIdx.x, tid = threadIdx.x;
    const float* wrow; __half* dst; int co, CoPad;
    if (co_all < 256)      { dst = g_wv; co = co_all;       CoPad = 256; wrow = w_val  + (size_t)co * 2304; }
    else if (co_all < 576) { dst = g_wp; co = co_all - 256; CoPad = 512; wrow = w_off  + (size_t)co * 2304; }
    else if (co_all < 736) { dst = g_wp; co = co_all - 256; CoPad = 512; wrow = w_attn + (size_t)(co - 320) * 2304; }
    else if (co_all < 768) {
        int co_p = co_all - 256;
#pragma unroll
        for (int shift = 0; shift < 9; shift++)
            g_wp[((size_t)(shift * 512 + co_p)) * 256 + tid] = __float2half(0.f);
        return;
    }
    else                   { dst = g_wu; co = co_all - 768; CoPad = 256; wrow = w_out + (size_t)co * 2304; }

    __shared__ float s[2304];
    for (int i = tid; i < 2304; i += 256) s[i] = wrow[i];
    __syncthreads();
#pragma unroll
    for (int shift = 0; shift < 9; shift++)
        dst[((size_t)(shift * CoPad + co)) * 256 + tid] = __float2half(s[tid * 9 + shift]);
}

// ================= 1-term HMMA implicit-GEMM 3x3 conv =================
#define BROWS  330
#define BBYTES (BROWS * 128)            // 42240
#define M_A_OFF  BBYTES                 // 42240
#define SMTOT_M  (BBYTES + 32768)       // 75008

__device__ __forceinline__ void conv_body1(char* smem,
    const __half* __restrict__ wgt, const __half* __restrict__ xh,
    const float* __restrict__ bias1, const float* __restrict__ bias2,
    float* __restrict__ out, int CoPad, int layout, int co0)
{
    const uint32_t sb = smem_u32(smem);
    const int tid = threadIdx.x, wid = tid >> 5, lane = tid & 31;
    const int warp_m = wid & 3, warp_n = wid >> 2;
    const int t = blockIdx.z, o0 = blockIdx.y << 7;
    const int pmin = o0 + 2 * (o0 / 96);

    float C[2][8][4];
#pragma unroll
    for (int m = 0; m < 2; m++)
#pragma unroll
        for (int n = 0; n < 8; n++)
#pragma unroll
            for (int k = 0; k < 4; k++) C[m][n][k] = 0.f;

    const int kh_b = (lane >> 3) & 1;
    const int kh_a = lane >> 4;
    int prow[4];
#pragma unroll
    for (int j = 0; j < 4; j++) {
        int nl = warp_n * 64 + j * 16 + ((lane >> 4) << 3) + (lane & 7);
        int o = o0 + nl;
        prow[j] = o + 2 * (o / 96) + 99 - pmin;
    }
    int arow[2];
#pragma unroll
    for (int m = 0; m < 2; m++) arow[m] = warp_m * 32 + m * 16 + (lane & 15);

    const int ac = tid & 7;
    uint32_t adof[4];
#pragma unroll
    for (int i = 0; i < 4; i++) {
        int ar = (tid >> 3) + i * 32;
        adof[i] = ar * 128 + ((ac ^ (ar & 7)) << 4);
    }

    auto fetch_A = [&](int cs, uint4* regs) {
        const int chunk = cs / 9, shift = cs - chunk * 9;
#pragma unroll
        for (int i = 0; i < 4; i++) {
            int row = (tid >> 3) + i * 32;
            regs[i] = *(const uint4*)((const char*)wgt +
                (((size_t)(shift * CoPad + co0 + row)) * 256 + chunk * 64) * 2 + ac * 16);
        }
    };
    auto store_A = [&](int buf, const uint4* regs) {
        char* st = smem + M_A_OFF + buf * 16384;
#pragma unroll
        for (int i = 0; i < 4; i++)
            *(uint4*)(st + adof[i]) = regs[i];
    };
    auto load_B = [&](int chunk) {
        const int prem = PPIX_ - pmin;
        const char* bh = (const char*)xh + (((size_t)t * PPIX_ + pmin) * 256 + chunk * 64) * 2;
#pragma unroll
        for (int i = 0; i < 11; i++) {
            int idx = tid + i * 256;
            if (idx < BROWS * 8) {
                int r = idx >> 3, c = idx & 7;
                uint32_t dof = r * 128 + ((c ^ (r & 7)) << 4);
                int ok = (r < prem);
                int rs = ok ? r : 0;
                cp16(sb + dof, bh + (size_t)rs * 512 + c * 16, ok);
            }
        }
    };

    load_B(0);
    {
        uint4 a0[4];
        fetch_A(0, a0);
        store_A(0, a0);
    }
    cp_async_wait_all();
    __syncthreads();

    for (int cs = 0; cs < 36; cs++) {
        const int shift = cs % 9;
        uint4 apre[4];
        if (cs + 1 < 36) fetch_A(cs + 1, apre);

        const uint32_t AS = sb + M_A_OFF + (cs & 1) * 16384;
        const int off = (shift / 3 - 1) * PW_ + (shift % 3 - 1);
#pragma unroll
        for (int ks = 0; ks < 4; ks++) {
            uint32_t a[2][4], b[4][4];
#pragma unroll
            for (int m = 0; m < 2; m++) {
                int c = ks * 2 + kh_a;
                ldsm4(a[m], AS + arow[m] * 128 + ((c ^ (arow[m] & 7)) << 4));
            }
#pragma unroll
            for (int j = 0; j < 4; j++) {
                int r = prow[j] + off;
                int c = ks * 2 + kh_b;
                ldsm4(b[j], sb + r * 128 + ((c ^ (r & 7)) << 4));
            }
#pragma unroll
            for (int m = 0; m < 2; m++)
#pragma unroll
                for (int n = 0; n < 8; n++)
                    mma16816(C[m][n], a[m], b[n >> 1][(n & 1) * 2], b[n >> 1][(n & 1) * 2 + 1]);
        }

        if (cs + 1 < 36) store_A((cs + 1) & 1, apre);
        if (shift == 8 && cs + 1 < 36) {
            __syncthreads();
            load_B(cs / 9 + 1);
            cp_async_wait_all();
        }
        __syncthreads();
    }

    // epilogue
#pragma unroll
    for (int m = 0; m < 2; m++) {
        const int coA = co0 + warp_m * 32 + m * 16 + (lane >> 2);
#pragma unroll
        for (int n = 0; n < 8; n++) {
            const int px = o0 + warp_n * 64 + n * 8 + ((lane & 3) << 1);
#pragma unroll
            for (int half = 0; half < 2; half++) {
                const int co = coA + half * 8;
                const float v0 = C[m][n][half * 2 + 0];
                const float v1 = C[m][n][half * 2 + 1];
                if (layout == 0) {
                    const float bv = bias1[co];
                    float* op = out + ((size_t)t * 256 + co) * HW_ + px;
                    op[0] = v0 + bv; op[1] = v1 + bv;
                } else if (layout == 1) {
                    const float bv = bias1[co];
                    const int head = co >> 5, dh = co & 31;
                    __half* op = g_value + (((size_t)(t * 8 + head) * HW_ + px) << 5) + dh;
                    op[0]  = __float2half(v0 + bv);
                    op[32] = __float2half(v1 + bv);
                } else {
                    if (co < 320) {
                        const int head = co / 40, within = co - head * 40;
                        const float bv = bias1[co];
                        float* op = g_off2 + (((size_t)t * HW_ + px) * 8 + head) * 40 + within;
                        op[0]   = v0 + bv;
                        op[320] = v1 + bv;
                    } else if (co < 480) {
                        const int c2 = co - 320;
                        const int head = c2 / 20, within = c2 - head * 20;
                        const float bv = bias2[c2];
                        float* op = g_attn2 + (((size_t)t * HW_ + px) * 8 + head) * 20 + within;
                        op[0]   = v0 + bv;
                        op[160] = v1 + bv;
                    }
                }
            }
        }
    }
}

__global__ void __launch_bounds__(256, 2) conv_main_kernel(
    const float* __restrict__ b_val, const float* __restrict__ b_off, const float* __restrict__ b_attn)
{
    extern __shared__ char smem[];
    if (blockIdx.x < 2)
        conv_body1(smem, g_wv, g_xfh, b_val, nullptr, nullptr, 256, 1, (int)blockIdx.x << 7);
    else
        conv_body1(smem, g_wp, g_xqh, b_off, b_attn, nullptr, 512, 2, ((int)blockIdx.x - 2) << 7);
}

__global__ void __launch_bounds__(256, 2) conv_out_kernel(
    const float* __restrict__ b_out, float* __restrict__ out)
{
    extern __shared__ char smem[];
    conv_body1(smem, g_wu, g_xsh, b_out, nullptr, out, 256, 0, (int)blockIdx.x << 7);
}

// ================= fused flow composition (single block) =================
__constant__ int c_flow_steps[9][3] = {
    {1,  7,  2},  {2, 13,  3},  {3, 19,  4},
    {7, 13,  8},  {8, 19,  9},  {13, 19, 14},
    {11, 5, 10},  {17, 11, 16}, {16, 5, 15},
};

__global__ void __launch_bounds__(1024) flow_all_kernel(
    const float* __restrict__ ff, const float* __restrict__ fb)
{
    const int tid = threadIdx.x;
    for (int p = tid; p < HW_; p += 1024) {
#pragma unroll
        for (int i = 0; i < 4; i++)
#pragma unroll
            for (int j = 0; j < 5; j++) {
                g_adds[((i * 5 + j) * 2 + 0) * HW_ + p] = 0.f;
                g_adds[((i * 5 + j) * 2 + 1) * HW_ + p] = 0.f;
            }
#pragma unroll
        for (int k = 0; k < 4; k++) {
            g_adds[((k * 5 + (k + 1)) * 2 + 0) * HW_ + p] = ff[(k * 2 + 0) * HW_ + p];
            g_adds[((k * 5 + (k + 1)) * 2 + 1) * HW_ + p] = ff[(k * 2 + 1) * HW_ + p];
        }
#pragma unroll
        for (int k = 0; k < 3; k++) {
            g_adds[(((k + 1) * 5 + k) * 2 + 0) * HW_ + p] = fb[(k * 2 + 0) * HW_ + p];
            g_adds[(((k + 1) * 5 + k) * 2 + 1) * HW_ + p] = fb[(k * 2 + 1) * HW_ + p];
        }
    }
    __syncthreads();
    for (int step = 0; step < 9; step++) {
        const float* bptr = g_adds + c_flow_steps[step][0] * 2 * HW_;
        const float* tgt  = g_adds + c_flow_steps[step][1] * 2 * HW_;
        float*       dst  = g_adds + c_flow_steps[step][2] * 2 * HW_;
        for (int p = tid; p < HW_; p += 1024) {
            int y = p / W_, x = p - y * W_;
            float fx = bptr[p], fy = bptr[HW_ + p];
            float px = (float)x + fx, py = (float)y + fy;
            float x0f = floorf(px), y0f = floorf(py);
            int   x0 = (int)x0f, y0 = (int)y0f;
            float wx1 = px - x0f, wx0 = 1.f - wx1;
            float wy1 = py - y0f, wy0 = 1.f - wy1;
            float s0 = 0.f, s1 = 0.f;
            const int xs[4] = {x0, x0 + 1, x0, x0 + 1};
            const int ys[4] = {y0, y0, y0 + 1, y0 + 1};
            const float ws[4] = {wx0 * wy0, wx1 * wy0, wx0 * wy1, wx1 * wy1};
#pragma unroll
            for (int k = 0; k < 4; k++) {
                if ((unsigned)xs[k] < W_ && (unsigned)ys[k] < H_) {
                    int idx = ys[k] * W_ + xs[k];
                    s0 = fmaf(tgt[idx], ws[k], s0);
                    s1 = fmaf(tgt[HW_ + idx], ws[k], s1);
                }
            }
            dst[p]       = fx + s0;
            dst[HW_ + p] = fy + s1;
        }
        __syncthreads();
    }
}

// ================= deformable sampling (4-way point-parallel, 4 ch/lane) =================
// Warp per (q, head). lane = pt(lane>>3) x cq(lane&7; channels 4cq..4cq+3).
// Each level: all 4 points in parallel -> 4 tap LDGs (uint2) -> 20 per item.
__global__ void __launch_bounds__(256) sample_kernel(const float* __restrict__ ref_pts)
{
    const int item = blockIdx.x * 8 + (threadIdx.x >> 5);
    const int lane = threadIdx.x & 31;
    const int pt   = lane >> 3;          // point 0..3
    const int cq   = lane & 7;           // channels 4cq..4cq+3
    const int head = item & 7;
    const int q    = item >> 3;
    const int t    = q / HW_;
    const int p    = q - t * HW_;
    const int ri   = (t == 4) ? 3 : t;

    // softmax logits: 20 contiguous floats (uniform across warp)
    const float* aw = g_attn2 + (((size_t)t * HW_ + p) * 8 + head) * 20;
    float lg[20];
#pragma unroll
    for (int i = 0; i < 5; i++) {
        float4 f = *(const float4*)(aw + i * 4);
        lg[i * 4 + 0] = f.x; lg[i * 4 + 1] = f.y; lg[i * 4 + 2] = f.z; lg[i * 4 + 3] = f.w;
    }
    float mx = -1e30f;
#pragma unroll
    for (int i = 0; i < 20; i++) mx = fmaxf(mx, lg[i]);
    float ssum = 0.f;
#pragma unroll
    for (int i = 0; i < 20; i++) { lg[i] = __expf(lg[i] - mx); ssum += lg[i]; }
    const float inv = 1.f / ssum;

    const float* ofp = g_off2 + (((size_t)t * HW_ + p) * 8 + head) * 40;
    float a0 = 0.f, a1 = 0.f, a2 = 0.f, a3 = 0.f;    // 4 channels, this lane's point
#pragma unroll
    for (int l = 0; l < LVLS_; l++) {
        const float ax = g_adds[((ri * 5 + l) * 2 + 0) * HW_ + p];
        const float ay = g_adds[((ri * 5 + l) * 2 + 1) * HW_ + p];
        const float rx = ref_pts[((size_t)q * 5 + l) * 2 + 0];
        const float ry = ref_pts[((size_t)q * 5 + l) * 2 + 1];
        float ox_l, oy_l;
        {
            float4 q0 = *(const float4*)(ofp + l * 8);
            float4 q1 = *(const float4*)(ofp + l * 8 + 4);
            // select this lane's point offsets
            ox_l = (pt == 0) ? q0.x : (pt == 1) ? q0.z : (pt == 2) ? q1.x : q1.z;
            oy_l = (pt == 0) ? q0.y : (pt == 1) ? q0.w : (pt == 2) ? q1.y : q1.w;
        }
        const __half* vimg = g_value + ((size_t)(l * 8 + head) * HW_ << 5) + 4 * cq;

        const float px = fmaf(rx, (float)W_, ox_l + ax) - 0.5f;
        const float py = fmaf(ry, (float)H_, oy_l + ay) - 0.5f;
        const float x0f = floorf(px), y0f = floorf(py);
        const int   x0 = (int)x0f, y0 = (int)y0f;
        const float wx1 = px - x0f, wx0 = 1.f - wx1;
        const float wy1 = py - y0f, wy0 = 1.f - wy1;
        const bool vx0 = (unsigned)x0 < W_,       vx1 = (unsigned)(x0 + 1) < W_;
        const bool vy0 = (unsigned)y0 < H_,       vy1 = (unsigned)(y0 + 1) < H_;
        const int xc0 = min(max(x0, 0), W_ - 1),  xc1 = min(max(x0 + 1, 0), W_ - 1);
        const int yc0 = min(max(y0, 0), H_ - 1),  yc1 = min(max(y0 + 1, 0), H_ - 1);
        const float w00 = (vx0 && vy0) ? wx0 * wy0 : 0.f;
        const float w01 = (vx1 && vy0) ? wx1 * wy0 : 0.f;
        const float w10 = (vx0 && vy1) ? wx0 * wy1 : 0.f;
        const float w11 = (vx1 && vy1) ? wx1 * wy1 : 0.f;
        const uint2 u00 = *(const uint2*)(vimg + (((size_t)(yc0 * W_ + xc0)) << 5));
        const uint2 u01 = *(const uint2*)(vimg + (((size_t)(yc0 * W_ + xc1)) << 5));
        const uint2 u10 = *(const uint2*)(vimg + (((size_t)(yc1 * W_ + xc0)) << 5));
        const uint2 u11 = *(const uint2*)(vimg + (((size_t)(yc1 * W_ + xc1)) << 5));
        const float2 a00 = __half22float2(*(const __half2*)&u00.x), b00 = __half22float2(*(const __half2*)&u00.y);
        const float2 a01 = __half22float2(*(const __half2*)&u01.x), b01 = __half22float2(*(const __half2*)&u01.y);
        const float2 a10 = __half22float2(*(const __half2*)&u10.x), b10 = __half22float2(*(const __half2*)&u10.y);
        const float2 a11 = __half22float2(*(const __half2*)&u11.x), b11 = __half22float2(*(const __half2*)&u11.y);
        const float wl = lg[l * 4 + pt] * inv;
        a0 = fmaf(a00.x * w00 + a01.x * w01 + a10.x * w10 + a11.x * w11, wl, a0);
        a1 = fmaf(a00.y * w00 + a01.y * w01 + a10.y * w10 + a11.y * w11, wl, a1);
        a2 = fmaf(b00.x * w00 + b01.x * w01 + b10.x * w10 + b11.x * w11, wl, a2);
        a3 = fmaf(b00.y * w00 + b01.y * w01 + b10.y * w10 + b11.y * w11, wl, a3);
    }
    // reduce over the 4 point-groups: lanes +16, then +8; result in lanes 0..7
    a0 += __shfl_down_sync(0xffffffffu, a0, 16);
    a1 += __shfl_down_sync(0xffffffffu, a1, 16);
    a2 += __shfl_down_sync(0xffffffffu, a2, 16);
    a3 += __shfl_down_sync(0xffffffffu, a3, 16);
    a0 += __shfl_down_sync(0xffffffffu, a0, 8);
    a1 += __shfl_down_sync(0xffffffffu, a1, 8);
    a2 += __shfl_down_sync(0xffffffffu, a2, 8);
    a3 += __shfl_down_sync(0xffffffffu, a3, 8);
    if (pt == 0) {
        const int y = p / 96, x = p - y * 96;
        const size_t ob = ((size_t)t * PPIX_ + (size_t)(y + 1) * PW_ + x + 1) * 256 + (head << 5) + 4 * cq;
        __half2 h0 = __floats2half2_rn(a0, a1);
        __half2 h1 = __floats2half2_rn(a2, a3);
        uint2 st;
        st.x = *(uint32_t*)&h0;
        st.y = *(uint32_t*)&h1;
        *(uint2*)(g_xsh + ob) = st;
    }
}

// ================= launch =================
extern "C" void kernel_launch(void* const* d_in, const int* in_sizes, int n_in,
                              void* d_out, int out_size)
{
    (void)in_sizes; (void)n_in; (void)out_size;
    const float* query         = (const float*)d_in[0];
    const float* input_flatten = (const float*)d_in[1];
    const float* ref_pts       = (const float*)d_in[2];
    const float* ff     = (const float*)d_in[6];
    const float* fb     = (const float*)d_in[7];
    const float* w_off  = (const float*)d_in[8];
    const float* b_off  = (const float*)d_in[9];
    const float* w_attn = (const float*)d_in[10];
    const float* b_attn = (const float*)d_in[11];
    const float* w_val  = (const float*)d_in[12];
    const float* b_val  = (const float*)d_in[13];
    const float* w_out  = (const float*)d_in[14];
    const float* b_out  = (const float*)d_in[15];
    float* out = (float*)d_out;

    cudaFuncSetAttribute(conv_main_kernel, cudaFuncAttributeMaxDynamicSharedMemorySize, SMTOT_M);
    cudaFuncSetAttribute(conv_out_kernel,  cudaFuncAttributeMaxDynamicSharedMemorySize, SMTOT_M);

    // 0: merged input prep
    prep_x_all_kernel<<<dim3(65, 5, 2), 128>>>(input_flatten, query);
    // 1: merged weight prep
    prep_w_all_kernel<<<1024, 256>>>(w_val, w_off, w_attn, w_out);
    // 2: flow composition
    flow_all_kernel<<<1, 1024>>>(ff, fb);
    // 3: merged value + off/attn convs (1-term)
    conv_main_kernel<<<dim3(6, 48, 5), 256, SMTOT_M>>>(b_val, b_off, b_attn);
    // 4: deformable attention sampling (4-way point-parallel)
    sample_kernel<<<(T_ * HW_ * HEADS_) / 8, 256>>>(ref_pts);
    // 5: output projection (1-term)
    conv_out_kernel<<<dim3(2, 48, 5), 256, SMTOT_M>>>(b_out, out);
}